// round 1
// baseline (speedup 1.0000x reference)
#include <cuda_runtime.h>
#include <math.h>

#define CC 128
#define NN 80000
#define EE 1000000
#define LL 400000
#define NBIN 4096
#define CAND_CAP 4096

// ---------------- device scratch (static, no allocs) ----------------
__device__ float g_score[2][NN];
__device__ int   g_hist[2][NBIN];
__device__ int   g_thrbin[2];
__device__ int   g_candcnt[2];
__device__ unsigned long long g_cand[2][CAND_CAP];
__device__ float g_Xt[2][CC * CC];
__device__ float g_W[2][CC * CC];
__device__ float g_xw[2][(size_t)NN * CC];
__device__ int   g_degs[2][NN];
__device__ int   g_degd[2][NN];
__device__ float g_h[2][(size_t)NN * CC];   // aggregated pre-relu outputs

// order-preserving float->uint key
__device__ __forceinline__ unsigned int ordkey(float f) {
    unsigned int u = __float_as_uint(f);
    return (u & 0x80000000u) ? ~u : (u | 0x80000000u);
}
__device__ __forceinline__ float ordval(unsigned int u) {
    u = (u & 0x80000000u) ? (u & 0x7FFFFFFFu) : ~u;
    return __uint_as_float(u);
}

// ---------------- score = x @ p / ||p||, + histogram ----------------
__global__ void k_score(const float* __restrict__ x, const float* __restrict__ p, int rel) {
    __shared__ __align__(16) float sp[CC];
    __shared__ float snorm;
    int tid = threadIdx.x;
    if (tid < CC) sp[tid] = p[tid];
    __syncthreads();
    if (tid == 0) {
        float s = 0.f;
        for (int i = 0; i < CC; i++) s += sp[i] * sp[i];
        snorm = sqrtf(s) + 1e-16f;
    }
    __syncthreads();
    int lane = tid & 31;
    int gw = (blockIdx.x * blockDim.x + tid) >> 5;
    if (gw < NN) {
        const float4* x4 = (const float4*)(x + (size_t)gw * CC);
        float4 xv = x4[lane];
        float4 pv = ((const float4*)sp)[lane];
        float d = xv.x * pv.x + xv.y * pv.y + xv.z * pv.z + xv.w * pv.w;
        #pragma unroll
        for (int o = 16; o > 0; o >>= 1) d += __shfl_down_sync(0xffffffffu, d, o);
        if (lane == 0) {
            float sc = d / snorm;
            g_score[rel][gw] = sc;
            atomicAdd(&g_hist[rel][ordkey(sc) >> 20], 1);
        }
    }
}

// ---------------- find threshold bin for top-128 ----------------
__global__ void k_thresh(int rel) {
    __shared__ int s[1024];
    int t = threadIdx.x;
    const int* h = g_hist[rel];
    int base = t * 4;
    s[t] = h[base] + h[base + 1] + h[base + 2] + h[base + 3];
    __syncthreads();
    if (t == 0) {
        long long acc = 0;
        int B = 0;
        for (int i = 1023; i >= 0; i--) {
            long long nacc = acc + s[i];
            if (nacc >= CC) {
                long long a2 = acc;
                int b;
                for (b = i * 4 + 3; b >= i * 4; b--) {
                    a2 += h[b];
                    if (a2 >= CC) break;
                }
                B = b;
                break;
            }
            acc = nacc;
        }
        g_thrbin[rel] = B;
        g_candcnt[rel] = 0;
    }
}

// ---------------- collect candidates >= threshold bin ----------------
__global__ void k_collect(int rel) {
    int i = blockIdx.x * blockDim.x + threadIdx.x;
    if (i >= NN) return;
    unsigned int k = ordkey(g_score[rel][i]);
    if ((int)(k >> 20) >= g_thrbin[rel]) {
        int pos = atomicAdd(&g_candcnt[rel], 1);
        if (pos < CAND_CAP)
            g_cand[rel][pos] = ((unsigned long long)k << 32)
                             | (unsigned long long)(0xFFFFFFFFu - (unsigned int)i);
    }
}

// ---------------- bitonic sort candidates, build X_tilde ----------------
__global__ void k_topsort(const float* __restrict__ x, int rel) {
    __shared__ unsigned long long a[CAND_CAP];
    __shared__ int   sidx[CC];
    __shared__ float sgate[CC];
    int t = threadIdx.x;
    int cnt = g_candcnt[rel];
    if (cnt > CAND_CAP) cnt = CAND_CAP;
    for (int i = t; i < CAND_CAP; i += 1024) a[i] = (i < cnt) ? g_cand[rel][i] : 0ULL;
    __syncthreads();
    for (int k = 2; k <= CAND_CAP; k <<= 1) {
        for (int j = k >> 1; j > 0; j >>= 1) {
            for (int i = t; i < CAND_CAP; i += 1024) {
                int ixj = i ^ j;
                if (ixj > i) {
                    bool up = ((i & k) == 0);   // ascending overall
                    unsigned long long A = a[i], B = a[ixj];
                    if ((A > B) == up) { a[i] = B; a[ixj] = A; }
                }
            }
            __syncthreads();
        }
    }
    if (t < CC) {
        unsigned long long key = a[CAND_CAP - 1 - t];     // rank t (descending)
        unsigned int kidx = 0xFFFFFFFFu - (unsigned int)(key & 0xFFFFFFFFu);
        float val = ordval((unsigned int)(key >> 32));
        sidx[t] = (int)kidx;
        sgate[t] = tanhf(val);
    }
    __syncthreads();
    for (int e = t; e < CC * CC; e += 1024) {
        int r = e >> 7, c = e & 127;
        g_Xt[rel][e] = x[(size_t)sidx[r] * CC + c] * sgate[r];
    }
}

// ---------------- GRU step -> evolved weight W ----------------
__global__ void k_gru(const float* __restrict__ W0, const float* __restrict__ Wih,
                      const float* __restrict__ Whh, const float* __restrict__ bih,
                      const float* __restrict__ bhh, int rel) {
    __shared__ __align__(16) float sx[CC];
    __shared__ __align__(16) float sw0[CC];
    __shared__ float sg[6 * CC];
    int i = blockIdx.x;
    int t = threadIdx.x;
    sx[t]  = g_Xt[rel][i * CC + t];
    sw0[t] = W0[i * CC + t];
    __syncthreads();
    int w = t >> 5, lane = t & 31;
    for (int o = w; o < 6 * CC; o += 4) {
        const float* vec;
        const float* M;
        float bias;
        if (o < 3 * CC) { vec = sx;  M = Wih + (size_t)o * CC;          bias = bih[o]; }
        else            { vec = sw0; M = Whh + (size_t)(o - 3*CC) * CC; bias = bhh[o - 3*CC]; }
        float4 m = ((const float4*)M)[lane];
        float4 v = ((const float4*)vec)[lane];
        float d = m.x * v.x + m.y * v.y + m.z * v.z + m.w * v.w;
        #pragma unroll
        for (int off = 16; off > 0; off >>= 1) d += __shfl_down_sync(0xffffffffu, d, off);
        if (lane == 0) sg[o] = d + bias;
    }
    __syncthreads();
    float ir = sg[t], iz = sg[t + 128], in2 = sg[t + 256];
    float hr = sg[384 + t], hz = sg[512 + t], hn = sg[640 + t];
    float r = 1.f / (1.f + expf(-(ir + hr)));
    float z = 1.f / (1.f + expf(-(iz + hz)));
    float n = tanhf(in2 + r * hn);
    g_W[rel][i * CC + t] = (1.f - z) * n + z * sw0[t];
}

// ---------------- degree histograms ----------------
__global__ void k_deg(const int* __restrict__ edge, int rel) {
    int e = blockIdx.x * blockDim.x + threadIdx.x;
    if (e < EE) {
        atomicAdd(&g_degs[rel][edge[e]], 1);
        atomicAdd(&g_degd[rel][edge[EE + e]], 1);
    }
}

// ---------------- GEMM: xw = x @ W  (W in smem, 64-row tiles) ----------------
#define RLP 65
#define GEMM_SH_FLOATS (128 * 128 + 128 * RLP)
#define GEMM_SH_BYTES  (GEMM_SH_FLOATS * 4)

__global__ void __launch_bounds__(256, 1) k_gemm(const float* __restrict__ x, int rel) {
    extern __shared__ float sh[];
    float* Ws  = sh;                 // [c*128 + j]
    float* XsT = sh + 128 * 128;     // [c*RLP + r]
    int t = threadIdx.x;
    const float* W = g_W[rel];
    for (int i = t; i < 128 * 128; i += 256) Ws[i] = W[i];
    size_t rowbase = (size_t)blockIdx.x * 64;
    const float4* x4 = (const float4*)(x + rowbase * CC);
    #pragma unroll
    for (int k = 0; k < 8; k++) {
        int idx = t + k * 256;           // 0..2047
        int row = idx >> 5;
        int c4  = idx & 31;
        float4 v = x4[(size_t)row * 32 + c4];
        XsT[(c4 * 4 + 0) * RLP + row] = v.x;
        XsT[(c4 * 4 + 1) * RLP + row] = v.y;
        XsT[(c4 * 4 + 2) * RLP + row] = v.z;
        XsT[(c4 * 4 + 3) * RLP + row] = v.w;
    }
    __syncthreads();
    int lane = t & 31;
    int cg = t >> 5;             // 0..7 -> 16-col group
    int colbase = cg * 16;
    float acc0[16], acc1[16];
    #pragma unroll
    for (int i = 0; i < 16; i++) { acc0[i] = 0.f; acc1[i] = 0.f; }
    #pragma unroll 4
    for (int c = 0; c < 128; c++) {
        float xa = XsT[c * RLP + lane];
        float xb = XsT[c * RLP + lane + 32];
        const float4* wr = (const float4*)(Ws + c * 128 + colbase);
        float4 w0 = wr[0], w1 = wr[1], w2 = wr[2], w3 = wr[3];
        float wv[16] = { w0.x, w0.y, w0.z, w0.w, w1.x, w1.y, w1.z, w1.w,
                         w2.x, w2.y, w2.z, w2.w, w3.x, w3.y, w3.z, w3.w };
        #pragma unroll
        for (int i = 0; i < 16; i++) { acc0[i] += xa * wv[i]; acc1[i] += xb * wv[i]; }
    }
    __syncthreads();
    float* buf = sh;             // 64 x 129 staging (reuses Ws region)
    #pragma unroll
    for (int i = 0; i < 16; i++) {
        buf[lane * 129 + colbase + i]        = acc0[i];
        buf[(lane + 32) * 129 + colbase + i] = acc1[i];
    }
    __syncthreads();
    float* out = g_xw[rel] + rowbase * CC;
    for (int e = t; e < 2048; e += 256) {
        int row = e >> 5, q = e & 31;
        float4 v = make_float4(buf[row * 129 + q * 4 + 0], buf[row * 129 + q * 4 + 1],
                               buf[row * 129 + q * 4 + 2], buf[row * 129 + q * 4 + 3]);
        ((float4*)out)[e] = v;
    }
}

// ---------------- edge scatter: warp per edge, vector RED ----------------
__global__ void k_scatter(const int* __restrict__ edge, int rel) {
    int gw = (blockIdx.x * blockDim.x + threadIdx.x) >> 5;
    int lane = threadIdx.x & 31;
    if (gw >= EE) return;
    int row = __ldg(&edge[gw]);
    int col = __ldg(&edge[EE + gw]);
    float ds = (float)g_degs[rel][row];
    float dd = (float)g_degd[rel][col];
    float norm = rsqrtf(ds) * rsqrtf(dd);   // endpoints always have deg >= 1
    const float4* src = (const float4*)(g_xw[rel] + (size_t)row * CC);
    float4 v = src[lane];
    float* dst = g_h[rel] + (size_t)col * CC + lane * 4;
    asm volatile("red.global.add.v4.f32 [%0], {%1,%2,%3,%4};"
                 :: "l"(dst), "f"(v.x * norm), "f"(v.y * norm),
                    "f"(v.z * norm), "f"(v.w * norm)
                 : "memory");
}

// ---------------- link scorer (relu fused) ----------------
__global__ void k_link(const int* __restrict__ eli, const float* __restrict__ Wp,
                       const float* __restrict__ bp, float* __restrict__ out) {
    __shared__ __align__(16) float swsum[CC];
    __shared__ float sb;
    int t = threadIdx.x;
    if (t < CC) swsum[t] = Wp[2 * t] + Wp[2 * t + 1];
    if (t == 0) sb = bp[0] + bp[1];
    __syncthreads();
    int gw = (blockIdx.x * blockDim.x + t) >> 5;
    int lane = t & 31;
    if (gw >= LL) return;
    int s = eli[gw], d = eli[LL + gw];
    const float4* hu = (const float4*)(g_h[1] + (size_t)s * CC);   // h_user = rel 1
    const float4* hi = (const float4*)(g_h[0] + (size_t)d * CC);   // h_item = rel 0
    float4 a = hu[lane], b = hi[lane];
    float4 w = ((const float4*)swsum)[lane];
    float acc = fmaxf(a.x, 0.f) * fmaxf(b.x, 0.f) * w.x
              + fmaxf(a.y, 0.f) * fmaxf(b.y, 0.f) * w.y
              + fmaxf(a.z, 0.f) * fmaxf(b.z, 0.f) * w.z
              + fmaxf(a.w, 0.f) * fmaxf(b.w, 0.f) * w.w;
    #pragma unroll
    for (int o = 16; o > 0; o >>= 1) acc += __shfl_down_sync(0xffffffffu, acc, o);
    if (lane == 0) out[gw] = acc + sb;
}

// ---------------- host launcher ----------------
extern "C" void kernel_launch(void* const* d_in, const int* in_sizes, int n_in,
                              void* d_out, int out_size) {
    (void)in_sizes; (void)n_in; (void)out_size;

    void *ph, *pc, *pds, *pdd, *pout;
    cudaGetSymbolAddress(&ph,  g_hist);
    cudaGetSymbolAddress(&pc,  g_candcnt);
    cudaGetSymbolAddress(&pds, g_degs);
    cudaGetSymbolAddress(&pdd, g_degd);
    cudaGetSymbolAddress(&pout, g_h);
    cudaMemsetAsync(ph,  0, sizeof(int) * 2 * NBIN, 0);
    cudaMemsetAsync(pc,  0, sizeof(int) * 2, 0);
    cudaMemsetAsync(pds, 0, sizeof(int) * 2 * NN, 0);
    cudaMemsetAsync(pdd, 0, sizeof(int) * 2 * NN, 0);
    cudaMemsetAsync(pout, 0, sizeof(float) * 2ULL * NN * CC, 0);

    cudaFuncSetAttribute(k_gemm, cudaFuncAttributeMaxDynamicSharedMemorySize, GEMM_SH_BYTES);

    for (int rel = 0; rel < 2; rel++) {
        const float* x    = (const float*)d_in[rel == 0 ? 0 : 1];
        const int*   edge = (const int*)  d_in[rel == 0 ? 2 : 3];
        int pbase = (rel == 0) ? 5 : 11;
        const float* p   = (const float*)d_in[pbase + 0];
        const float* W0  = (const float*)d_in[pbase + 1];
        const float* Wih = (const float*)d_in[pbase + 2];
        const float* Whh = (const float*)d_in[pbase + 3];
        const float* bih = (const float*)d_in[pbase + 4];
        const float* bhh = (const float*)d_in[pbase + 5];

        k_score<<<(NN * 32 + 255) / 256, 256>>>(x, p, rel);
        k_thresh<<<1, 1024>>>(rel);
        k_collect<<<(NN + 255) / 256, 256>>>(rel);
        k_topsort<<<1, 1024>>>(x, rel);
        k_gru<<<CC, CC>>>(W0, Wih, Whh, bih, bhh, rel);
        k_deg<<<(EE + 255) / 256, 256>>>(edge, rel);
        k_gemm<<<NN / 64, 256, GEMM_SH_BYTES>>>(x, rel);
        k_scatter<<<(EE * 32 + 255) / 256, 256>>>(edge, rel);
    }

    k_link<<<((size_t)LL * 32 + 255) / 256, 256>>>((const int*)d_in[4],
                                                   (const float*)d_in[17],
                                                   (const float*)d_in[18],
                                                   (float*)d_out);
}

// round 2
// speedup vs baseline: 1.4588x; 1.4588x over previous
#include <cuda_runtime.h>
#include <math.h>

#define CC 128
#define NN 80000
#define EE 1000000
#define LL 400000
#define NBIN 4096
#define CAND_CAP 4096

// ---------------- device scratch (static, no allocs) ----------------
__device__ float g_score[2][NN];
__device__ int   g_hist[2][NBIN];
__device__ float g_Xt[2][CC * CC];
__device__ float g_W[2][CC * CC];
__device__ float g_xw[2][(size_t)NN * CC];   // pre-scaled by inv_s
__device__ int   g_degs[2][NN];
__device__ int   g_degd[2][NN];
__device__ int   g_off[2][NN + 1];
__device__ int   g_cursor[2][NN];
__device__ int   g_srt[2][EE];               // row indices bucketed by dst col
__device__ float g_h[2][(size_t)NN * CC];    // relu'd aggregated outputs

struct RelParams {
    const float* W0; const float* Wih; const float* Whh;
    const float* bih; const float* bhh;
};

// order-preserving float->uint key
__device__ __forceinline__ unsigned int ordkey(float f) {
    unsigned int u = __float_as_uint(f);
    return (u & 0x80000000u) ? ~u : (u | 0x80000000u);
}
__device__ __forceinline__ float ordval(unsigned int u) {
    u = (u & 0x80000000u) ? (u & 0x7FFFFFFFu) : ~u;
    return __uint_as_float(u);
}

// ---------------- score = x @ p / ||p||, + histogram (both rels) ----------------
__global__ void k_score(const float* __restrict__ x0, const float* __restrict__ x1,
                        const float* __restrict__ p0, const float* __restrict__ p1) {
    int rel = blockIdx.y;
    const float* x = rel ? x1 : x0;
    const float* p = rel ? p1 : p0;
    __shared__ __align__(16) float sp[CC];
    __shared__ float snorm;
    int tid = threadIdx.x;
    if (tid < CC) sp[tid] = p[tid];
    __syncthreads();
    if (tid == 0) {
        float s = 0.f;
        for (int i = 0; i < CC; i++) s += sp[i] * sp[i];
        snorm = sqrtf(s) + 1e-16f;
    }
    __syncthreads();
    int lane = tid & 31;
    int gw = (blockIdx.x * blockDim.x + tid) >> 5;
    if (gw < NN) {
        const float4* x4 = (const float4*)(x + (size_t)gw * CC);
        float4 xv = x4[lane];
        float4 pv = ((const float4*)sp)[lane];
        float d = xv.x * pv.x + xv.y * pv.y + xv.z * pv.z + xv.w * pv.w;
        #pragma unroll
        for (int o = 16; o > 0; o >>= 1) d += __shfl_down_sync(0xffffffffu, d, o);
        if (lane == 0) {
            float sc = d / snorm;
            g_score[rel][gw] = sc;
            atomicAdd(&g_hist[rel][ordkey(sc) >> 20], 1);
        }
    }
}

// ---------------- fused: threshold + collect + rank-select + X_tilde ----------------
__global__ void k_select(const float* __restrict__ x0, const float* __restrict__ x1) {
    int rel = blockIdx.x;
    const float* x = rel ? x1 : x0;
    __shared__ int s[1024];
    __shared__ int sB, scnt;
    __shared__ unsigned long long cand[CAND_CAP];
    __shared__ int   sidx[CC];
    __shared__ float sgate[CC];
    int t = threadIdx.x;
    const int* h = g_hist[rel];
    int b4 = t * 4;
    int v = h[b4] + h[b4 + 1] + h[b4 + 2] + h[b4 + 3];
    if (t == 0) scnt = 0;
    s[t] = v;
    __syncthreads();
    // inclusive suffix scan over 1024 groups
    for (int off = 1; off < 1024; off <<= 1) {
        int u = (t + off < 1024) ? s[t + off] : 0;
        __syncthreads();
        s[t] += u;
        __syncthreads();
    }
    int snext = (t < 1023) ? s[t + 1] : 0;
    if (s[t] >= CC && snext < CC) {
        int acc = snext;
        int B = b4;
        for (int b = b4 + 3; b >= b4; b--) {
            acc += h[b];
            if (acc >= CC) { B = b; break; }
        }
        sB = B;
    }
    __syncthreads();
    int B = sB;
    // collect candidates
    for (int i = t; i < NN; i += 1024) {
        unsigned int k = ordkey(g_score[rel][i]);
        if ((int)(k >> 20) >= B) {
            int pos = atomicAdd(&scnt, 1);
            if (pos < CAND_CAP)
                cand[pos] = ((unsigned long long)k << 32)
                          | (unsigned long long)(0xFFFFFFFFu - (unsigned int)i);
        }
    }
    __syncthreads();
    int c = min(scnt, CAND_CAP);
    // rank by counting (c ~ a few hundred)
    for (int i = t; i < c; i += 1024) {
        unsigned long long ki = cand[i];
        int r = 0;
        for (int j = 0; j < c; j++) r += (cand[j] > ki);
        if (r < CC) {
            sidx[r]  = (int)(0xFFFFFFFFu - (unsigned int)(ki & 0xFFFFFFFFu));
            sgate[r] = tanhf(ordval((unsigned int)(ki >> 32)));
        }
    }
    __syncthreads();
    for (int e = t; e < CC * CC; e += 1024) {
        int r = e >> 7, col = e & 127;
        g_Xt[rel][e] = x[(size_t)sidx[r] * CC + col] * sgate[r];
    }
}

// ---------------- GRU step -> evolved weight W (both rels) ----------------
__global__ void k_gru(RelParams r0, RelParams r1) {
    int rel = blockIdx.y;
    RelParams rp = rel ? r1 : r0;
    __shared__ __align__(16) float sx[CC];
    __shared__ __align__(16) float sw0[CC];
    __shared__ float sg[6 * CC];
    int i = blockIdx.x;
    int t = threadIdx.x;
    sx[t]  = g_Xt[rel][i * CC + t];
    sw0[t] = rp.W0[i * CC + t];
    __syncthreads();
    int w = t >> 5, lane = t & 31;
    for (int o = w; o < 6 * CC; o += 4) {
        const float* vec;
        const float* M;
        float bias;
        if (o < 3 * CC) { vec = sx;  M = rp.Wih + (size_t)o * CC;            bias = rp.bih[o]; }
        else            { vec = sw0; M = rp.Whh + (size_t)(o - 3*CC) * CC;   bias = rp.bhh[o - 3*CC]; }
        float4 m = ((const float4*)M)[lane];
        float4 v = ((const float4*)vec)[lane];
        float d = m.x * v.x + m.y * v.y + m.z * v.z + m.w * v.w;
        #pragma unroll
        for (int off = 16; off > 0; off >>= 1) d += __shfl_down_sync(0xffffffffu, d, off);
        if (lane == 0) sg[o] = d + bias;
    }
    __syncthreads();
    float ir = sg[t], iz = sg[t + 128], in2 = sg[t + 256];
    float hr = sg[384 + t], hz = sg[512 + t], hn = sg[640 + t];
    float r = 1.f / (1.f + expf(-(ir + hr)));
    float z = 1.f / (1.f + expf(-(iz + hz)));
    float n = tanhf(in2 + r * hn);
    g_W[rel][i * CC + t] = (1.f - z) * n + z * sw0[t];
}

// ---------------- degree histograms (both rels) ----------------
__global__ void k_deg(const int* __restrict__ e0, const int* __restrict__ e1) {
    int rel = blockIdx.y;
    const int* edge = rel ? e1 : e0;
    int e = blockIdx.x * blockDim.x + threadIdx.x;
    if (e < EE) {
        atomicAdd(&g_degs[rel][edge[e]], 1);
        atomicAdd(&g_degd[rel][edge[EE + e]], 1);
    }
}

// ---------------- prefix-scan degd -> offsets + cursor ----------------
__global__ void k_scan() {
    int rel = blockIdx.x;
    __shared__ int wsum[32];
    __shared__ int carry;
    int t = threadIdx.x, lane = t & 31, w = t >> 5;
    if (t == 0) carry = 0;
    __syncthreads();
    for (int base = 0; base < NN; base += 1024) {
        int i = base + t;
        int v = (i < NN) ? g_degd[rel][i] : 0;
        int inc = v;
        #pragma unroll
        for (int off = 1; off < 32; off <<= 1) {
            int u = __shfl_up_sync(0xffffffffu, inc, off);
            if (lane >= off) inc += u;
        }
        if (lane == 31) wsum[w] = inc;
        __syncthreads();
        if (w == 0) {
            int xv = wsum[lane];
            int ws = xv;
            #pragma unroll
            for (int off = 1; off < 32; off <<= 1) {
                int u = __shfl_up_sync(0xffffffffu, ws, off);
                if (lane >= off) ws += u;
            }
            wsum[lane] = ws - xv;   // exclusive warp prefix
        }
        __syncthreads();
        int incl = inc + wsum[w] + carry;
        if (i < NN) {
            g_off[rel][i + 1]  = incl;
            g_cursor[rel][i]   = incl - v;
        }
        __syncthreads();
        if (t == 1023) carry = incl;
        __syncthreads();
    }
    if (t == 0) g_off[rel][0] = 0;
}

// ---------------- bucket edges by dst ----------------
__global__ void k_fill(const int* __restrict__ e0, const int* __restrict__ e1) {
    int rel = blockIdx.y;
    const int* edge = rel ? e1 : e0;
    int e = blockIdx.x * blockDim.x + threadIdx.x;
    if (e < EE) {
        int row = edge[e];
        int col = edge[EE + e];
        int pos = atomicAdd(&g_cursor[rel][col], 1);
        g_srt[rel][pos] = row;
    }
}

// ---------------- GEMM: xw = (x @ W) * inv_s  (both rels) ----------------
#define RLP 65
#define GEMM_SH_FLOATS (128 * 128 + 128 * RLP)
#define GEMM_SH_BYTES  (GEMM_SH_FLOATS * 4)

__global__ void __launch_bounds__(256) k_gemm(const float* __restrict__ x0,
                                              const float* __restrict__ x1) {
    extern __shared__ float sh[];
    __shared__ float sscale[64];
    int rel = blockIdx.y;
    const float* x = rel ? x1 : x0;
    float* Ws  = sh;                 // [c*128 + j]
    float* XsT = sh + 128 * 128;     // [c*RLP + r]
    int t = threadIdx.x;
    const float* W = g_W[rel];
    for (int i = t; i < 128 * 128; i += 256) Ws[i] = W[i];
    size_t rowbase = (size_t)blockIdx.x * 64;
    const float4* x4 = (const float4*)(x + rowbase * CC);
    #pragma unroll
    for (int k = 0; k < 8; k++) {
        int idx = t + k * 256;
        int row = idx >> 5;
        int c4  = idx & 31;
        float4 v = x4[(size_t)row * 32 + c4];
        XsT[(c4 * 4 + 0) * RLP + row] = v.x;
        XsT[(c4 * 4 + 1) * RLP + row] = v.y;
        XsT[(c4 * 4 + 2) * RLP + row] = v.z;
        XsT[(c4 * 4 + 3) * RLP + row] = v.w;
    }
    if (t < 64) {
        int d = g_degs[rel][rowbase + t];
        sscale[t] = (d > 0) ? rsqrtf((float)d) : 0.f;
    }
    __syncthreads();
    int lane = t & 31;
    int cg = t >> 5;
    int colbase = cg * 16;
    float acc0[16], acc1[16];
    #pragma unroll
    for (int i = 0; i < 16; i++) { acc0[i] = 0.f; acc1[i] = 0.f; }
    #pragma unroll 4
    for (int c = 0; c < 128; c++) {
        float xa = XsT[c * RLP + lane];
        float xb = XsT[c * RLP + lane + 32];
        const float4* wr = (const float4*)(Ws + c * 128 + colbase);
        float4 w0 = wr[0], w1 = wr[1], w2 = wr[2], w3 = wr[3];
        float wv[16] = { w0.x, w0.y, w0.z, w0.w, w1.x, w1.y, w1.z, w1.w,
                         w2.x, w2.y, w2.z, w2.w, w3.x, w3.y, w3.z, w3.w };
        #pragma unroll
        for (int i = 0; i < 16; i++) { acc0[i] += xa * wv[i]; acc1[i] += xb * wv[i]; }
    }
    __syncthreads();
    float* buf = sh;             // 64 x 129 staging
    #pragma unroll
    for (int i = 0; i < 16; i++) {
        buf[lane * 129 + colbase + i]        = acc0[i];
        buf[(lane + 32) * 129 + colbase + i] = acc1[i];
    }
    __syncthreads();
    float* out = g_xw[rel] + rowbase * CC;
    for (int e = t; e < 2048; e += 256) {
        int row = e >> 5, q = e & 31;
        float sc = sscale[row];
        float4 v = make_float4(buf[row * 129 + q * 4 + 0] * sc,
                               buf[row * 129 + q * 4 + 1] * sc,
                               buf[row * 129 + q * 4 + 2] * sc,
                               buf[row * 129 + q * 4 + 3] * sc);
        ((float4*)out)[e] = v;
    }
}

// ---------------- CSR aggregate: warp per dst node, relu fused ----------------
__global__ void k_agg() {
    int rel = blockIdx.y;
    int gw = (blockIdx.x * blockDim.x + threadIdx.x) >> 5;
    int lane = threadIdx.x & 31;
    if (gw >= NN) return;
    int start = g_off[rel][gw];
    int end   = g_off[rel][gw + 1];
    const float4* xw = (const float4*)g_xw[rel];
    const int* srt = g_srt[rel];
    float4 acc = make_float4(0.f, 0.f, 0.f, 0.f);
    for (int base = start; base < end; base += 32) {
        int n = min(32, end - base);
        int r = (base + lane < end) ? srt[base + lane] : 0;
        for (int k = 0; k < n; k++) {
            int row = __shfl_sync(0xffffffffu, r, k);
            float4 v = xw[(size_t)row * 32 + lane];
            acc.x += v.x; acc.y += v.y; acc.z += v.z; acc.w += v.w;
        }
    }
    int d = end - start;
    float s = (d > 0) ? rsqrtf((float)d) : 0.f;
    float4 o = make_float4(fmaxf(acc.x * s, 0.f), fmaxf(acc.y * s, 0.f),
                           fmaxf(acc.z * s, 0.f), fmaxf(acc.w * s, 0.f));
    ((float4*)g_h[rel])[(size_t)gw * 32 + lane] = o;
}

// ---------------- link scorer (h already relu'd) ----------------
__global__ void k_link(const int* __restrict__ eli, const float* __restrict__ Wp,
                       const float* __restrict__ bp, float* __restrict__ out) {
    __shared__ __align__(16) float swsum[CC];
    __shared__ float sb;
    int t = threadIdx.x;
    if (t < CC) swsum[t] = Wp[2 * t] + Wp[2 * t + 1];
    if (t == 0) sb = bp[0] + bp[1];
    __syncthreads();
    int gw = (blockIdx.x * blockDim.x + t) >> 5;
    int lane = t & 31;
    if (gw >= LL) return;
    int s = eli[gw], d = eli[LL + gw];
    const float4* hu = (const float4*)(g_h[1] + (size_t)s * CC);
    const float4* hi = (const float4*)(g_h[0] + (size_t)d * CC);
    float4 a = hu[lane], b = hi[lane];
    float4 w = ((const float4*)swsum)[lane];
    float acc = a.x * b.x * w.x + a.y * b.y * w.y + a.z * b.z * w.z + a.w * b.w * w.w;
    #pragma unroll
    for (int o = 16; o > 0; o >>= 1) acc += __shfl_down_sync(0xffffffffu, acc, o);
    if (lane == 0) out[gw] = acc + sb;
}

// ---------------- host launcher ----------------
extern "C" void kernel_launch(void* const* d_in, const int* in_sizes, int n_in,
                              void* d_out, int out_size) {
    (void)in_sizes; (void)n_in; (void)out_size;

    void *ph, *pds, *pdd;
    cudaGetSymbolAddress(&ph,  g_hist);
    cudaGetSymbolAddress(&pds, g_degs);
    cudaGetSymbolAddress(&pdd, g_degd);
    cudaMemsetAsync(ph,  0, sizeof(int) * 2 * NBIN, 0);
    cudaMemsetAsync(pds, 0, sizeof(int) * 2 * NN, 0);
    cudaMemsetAsync(pdd, 0, sizeof(int) * 2 * NN, 0);

    cudaFuncSetAttribute(k_gemm, cudaFuncAttributeMaxDynamicSharedMemorySize, GEMM_SH_BYTES);

    const float* x0 = (const float*)d_in[0];
    const float* x1 = (const float*)d_in[1];
    const int*   e0 = (const int*)d_in[2];
    const int*   e1 = (const int*)d_in[3];

    RelParams r0 = { (const float*)d_in[6],  (const float*)d_in[7],
                     (const float*)d_in[8],  (const float*)d_in[9],
                     (const float*)d_in[10] };
    RelParams r1 = { (const float*)d_in[12], (const float*)d_in[13],
                     (const float*)d_in[14], (const float*)d_in[15],
                     (const float*)d_in[16] };

    dim3 gScore((NN * 32 + 255) / 256, 2);
    k_score<<<gScore, 256>>>(x0, x1, (const float*)d_in[5], (const float*)d_in[11]);

    dim3 gDeg((EE + 255) / 256, 2);
    k_deg<<<gDeg, 256>>>(e0, e1);

    k_select<<<2, 1024>>>(x0, x1);
    k_gru<<<dim3(CC, 2), CC>>>(r0, r1);
    k_scan<<<2, 1024>>>();
    k_fill<<<gDeg, 256>>>(e0, e1);

    k_gemm<<<dim3(NN / 64, 2), 256, GEMM_SH_BYTES>>>(x0, x1);

    dim3 gAgg((NN * 32 + 255) / 256, 2);
    k_agg<<<gAgg, 256>>>();

    k_link<<<(LL * 32 + 255) / 256, 256>>>((const int*)d_in[4],
                                           (const float*)d_in[17],
                                           (const float*)d_in[18],
                                           (float*)d_out);
}

// round 3
// speedup vs baseline: 1.8049x; 1.2372x over previous
#include <cuda_runtime.h>
#include <math.h>

#define CC 128
#define NN 80000
#define EE 1000000
#define LL 400000
#define NBIN 4096
#define CAND_CAP 4096
#define SCAN_BLK 79   // ceil(80000/1024)

// ---------------- device scratch (static, no allocs) ----------------
__device__ float g_score[2][NN];
__device__ int   g_hist[2][NBIN];
__device__ float g_Xt[2][CC * CC];
__device__ float g_gi[2][CC * 3 * CC];
__device__ float g_gh[2][CC * 3 * CC];
__device__ float g_W[2][CC * CC];
__device__ float g_xw[2][(size_t)NN * CC];   // pre-scaled by inv_s
__device__ int   g_degs[2][NN];
__device__ int   g_degd[2][NN];
__device__ int   g_off[2][NN + 1];
__device__ int   g_cursor[2][NN];
__device__ int   g_bsum[2][128];
__device__ int   g_boff[2][128];
__device__ int   g_srt[2][EE];               // row indices bucketed by dst col
__device__ float g_h[2][(size_t)NN * CC];    // relu'd aggregated outputs

struct RelParams {
    const float* W0; const float* Wih; const float* Whh;
    const float* bih; const float* bhh;
};

// order-preserving float->uint key
__device__ __forceinline__ unsigned int ordkey(float f) {
    unsigned int u = __float_as_uint(f);
    return (u & 0x80000000u) ? ~u : (u | 0x80000000u);
}
__device__ __forceinline__ float ordval(unsigned int u) {
    u = (u & 0x80000000u) ? (u & 0x7FFFFFFFu) : ~u;
    return __uint_as_float(u);
}

// ---------------- score = x @ p / ||p||, + histogram (both rels) ----------------
__global__ void k_score(const float* __restrict__ x0, const float* __restrict__ x1,
                        const float* __restrict__ p0, const float* __restrict__ p1) {
    int rel = blockIdx.y;
    const float* x = rel ? x1 : x0;
    const float* p = rel ? p1 : p0;
    __shared__ __align__(16) float sp[CC];
    __shared__ float snorm;
    int tid = threadIdx.x;
    if (tid < CC) sp[tid] = p[tid];
    __syncthreads();
    if (tid == 0) {
        float s = 0.f;
        for (int i = 0; i < CC; i++) s += sp[i] * sp[i];
        snorm = sqrtf(s) + 1e-16f;
    }
    __syncthreads();
    int lane = tid & 31;
    int gw = (blockIdx.x * blockDim.x + tid) >> 5;
    if (gw < NN) {
        const float4* x4 = (const float4*)(x + (size_t)gw * CC);
        float4 xv = x4[lane];
        float4 pv = ((const float4*)sp)[lane];
        float d = xv.x * pv.x + xv.y * pv.y + xv.z * pv.z + xv.w * pv.w;
        #pragma unroll
        for (int o = 16; o > 0; o >>= 1) d += __shfl_down_sync(0xffffffffu, d, o);
        if (lane == 0) {
            float sc = d / snorm;
            g_score[rel][gw] = sc;
            atomicAdd(&g_hist[rel][ordkey(sc) >> 20], 1);
        }
    }
}

// ---------------- fused: threshold + collect + rank-select + X_tilde ----------------
__global__ void k_select(const float* __restrict__ x0, const float* __restrict__ x1) {
    int rel = blockIdx.x;
    const float* x = rel ? x1 : x0;
    __shared__ int s[1024];
    __shared__ int sB, scnt;
    __shared__ unsigned long long cand[CAND_CAP];
    __shared__ int   sidx[CC];
    __shared__ float sgate[CC];
    int t = threadIdx.x;
    const int* h = g_hist[rel];
    int b4 = t * 4;
    int v = h[b4] + h[b4 + 1] + h[b4 + 2] + h[b4 + 3];
    if (t == 0) scnt = 0;
    s[t] = v;
    __syncthreads();
    for (int off = 1; off < 1024; off <<= 1) {
        int u = (t + off < 1024) ? s[t + off] : 0;
        __syncthreads();
        s[t] += u;
        __syncthreads();
    }
    int snext = (t < 1023) ? s[t + 1] : 0;
    if (s[t] >= CC && snext < CC) {
        int acc = snext;
        int B = b4;
        for (int b = b4 + 3; b >= b4; b--) {
            acc += h[b];
            if (acc >= CC) { B = b; break; }
        }
        sB = B;
    }
    __syncthreads();
    int B = sB;
    for (int i = t; i < NN; i += 1024) {
        unsigned int k = ordkey(g_score[rel][i]);
        if ((int)(k >> 20) >= B) {
            int pos = atomicAdd(&scnt, 1);
            if (pos < CAND_CAP)
                cand[pos] = ((unsigned long long)k << 32)
                          | (unsigned long long)(0xFFFFFFFFu - (unsigned int)i);
        }
    }
    __syncthreads();
    int c = min(scnt, CAND_CAP);
    for (int i = t; i < c; i += 1024) {
        unsigned long long ki = cand[i];
        int r = 0;
        for (int j = 0; j < c; j++) r += (cand[j] > ki);
        if (r < CC) {
            sidx[r]  = (int)(0xFFFFFFFFu - (unsigned int)(ki & 0xFFFFFFFFu));
            sgate[r] = tanhf(ordval((unsigned int)(ki >> 32)));
        }
    }
    __syncthreads();
    for (int e = t; e < CC * CC; e += 1024) {
        int r = e >> 7, col = e & 127;
        g_Xt[rel][e] = x[(size_t)sidx[r] * CC + col] * sgate[r];
    }
}

// ---------------- GRU GEMMs: gi = Xt@Wih^T, gh = W0@Whh^T ----------------
// grid (6, 2, 2): x = 64-col tile of 384, y = rel, z = src (0=gi,1=gh)
#define PA 132
#define PM 68
#define GRUMM_SH_BYTES ((128 * PA + 128 * PM) * 4)

__global__ void __launch_bounds__(256) k_grumm(RelParams r0, RelParams r1) {
    extern __shared__ float sh[];
    float* Ast = sh;              // [c*PA + i]
    float* Ms  = sh + 128 * PA;   // [c*PM + jl]
    int rel = blockIdx.y, src = blockIdx.z, bx = blockIdx.x;
    RelParams rp = rel ? r1 : r0;
    const float* A = src ? rp.W0 : g_Xt[rel];
    const float* M = (src ? rp.Whh : rp.Wih) + (size_t)bx * 64 * 128;
    float* out = (src ? g_gh[rel] : g_gi[rel]);
    int t = threadIdx.x;
    #pragma unroll
    for (int n = 0; n < 64; n += 4) {
        int idx = t + (n >> 2) * 4096;   // dummy, replaced below
    }
    // load A transposed
    for (int idx = t; idx < 128 * 128; idx += 256) {
        int i = idx >> 7, c = idx & 127;
        Ast[c * PA + i] = A[idx];
    }
    // load M tile transposed
    for (int idx = t; idx < 64 * 128; idx += 256) {
        int jl = idx >> 7, c = idx & 127;
        Ms[c * PM + jl] = M[idx];
    }
    __syncthreads();
    int tx = t & 15;         // col group of 4
    int ty = t >> 4;         // row group of 8
    float acc[8][4];
    #pragma unroll
    for (int i = 0; i < 8; i++)
        #pragma unroll
        for (int j = 0; j < 4; j++) acc[i][j] = 0.f;
    #pragma unroll 2
    for (int k = 0; k < 128; k++) {
        float4 a0 = *(const float4*)&Ast[k * PA + ty * 8];
        float4 a1 = *(const float4*)&Ast[k * PA + ty * 8 + 4];
        float4 b  = *(const float4*)&Ms[k * PM + tx * 4];
        float av[8] = { a0.x, a0.y, a0.z, a0.w, a1.x, a1.y, a1.z, a1.w };
        #pragma unroll
        for (int i = 0; i < 8; i++) {
            acc[i][0] += av[i] * b.x;
            acc[i][1] += av[i] * b.y;
            acc[i][2] += av[i] * b.z;
            acc[i][3] += av[i] * b.w;
        }
    }
    #pragma unroll
    for (int i = 0; i < 8; i++) {
        int row = ty * 8 + i;
        int col = bx * 64 + tx * 4;
        *(float4*)&out[row * 384 + col] =
            make_float4(acc[i][0], acc[i][1], acc[i][2], acc[i][3]);
    }
}

// ---------------- GRU gates -> evolved W ----------------
__global__ void k_gate(RelParams r0, RelParams r1) {
    int rel = blockIdx.y;
    RelParams rp = rel ? r1 : r0;
    int i = blockIdx.x;
    int t = threadIdx.x;
    const float* gi = g_gi[rel] + i * 384;
    const float* gh = g_gh[rel] + i * 384;
    float ir = gi[t]       + rp.bih[t];
    float iz = gi[t + 128] + rp.bih[t + 128];
    float in2 = gi[t + 256] + rp.bih[t + 256];
    float hr = gh[t]       + rp.bhh[t];
    float hz = gh[t + 128] + rp.bhh[t + 128];
    float hn = gh[t + 256] + rp.bhh[t + 256];
    float w0 = rp.W0[i * CC + t];
    float r = 1.f / (1.f + expf(-(ir + hr)));
    float z = 1.f / (1.f + expf(-(iz + hz)));
    float n = tanhf(in2 + r * hn);
    g_W[rel][i * CC + t] = (1.f - z) * n + z * w0;
}

// ---------------- degree histograms (both rels) ----------------
__global__ void k_deg(const int* __restrict__ e0, const int* __restrict__ e1) {
    int rel = blockIdx.y;
    const int* edge = rel ? e1 : e0;
    int e = blockIdx.x * blockDim.x + threadIdx.x;
    if (e < EE) {
        atomicAdd(&g_degs[rel][edge[e]], 1);
        atomicAdd(&g_degd[rel][edge[EE + e]], 1);
    }
}

// ---------------- hierarchical scan of degd ----------------
__global__ void k_scan1() {
    int rel = blockIdx.y, b = blockIdx.x;
    __shared__ int wsum[32];
    int t = threadIdx.x, lane = t & 31, w = t >> 5;
    int i = b * 1024 + t;
    int v = (i < NN) ? g_degd[rel][i] : 0;
    int inc = v;
    #pragma unroll
    for (int off = 1; off < 32; off <<= 1) {
        int u = __shfl_up_sync(0xffffffffu, inc, off);
        if (lane >= off) inc += u;
    }
    if (lane == 31) wsum[w] = inc;
    __syncthreads();
    if (w == 0) {
        int xv = wsum[lane];
        int ws = xv;
        #pragma unroll
        for (int off = 1; off < 32; off <<= 1) {
            int u = __shfl_up_sync(0xffffffffu, ws, off);
            if (lane >= off) ws += u;
        }
        wsum[lane] = ws - xv;
    }
    __syncthreads();
    int incl = inc + wsum[w];
    if (i < NN) g_off[rel][i + 1] = incl;   // local inclusive (no block offset yet)
    if (t == 1023) g_bsum[rel][b] = incl;
}

__global__ void k_scan2() {
    int rel = blockIdx.x;
    __shared__ int s[SCAN_BLK];
    int t = threadIdx.x;
    if (t < SCAN_BLK) s[t] = g_bsum[rel][t];
    __syncthreads();
    if (t == 0) {
        int acc = 0;
        for (int b = 0; b < SCAN_BLK; b++) {
            g_boff[rel][b] = acc;
            acc += s[b];
        }
    }
}

__global__ void k_scan3() {
    int rel = blockIdx.y, b = blockIdx.x;
    int t = threadIdx.x;
    int i = b * 1024 + t;
    if (i < NN) {
        int o = g_off[rel][i + 1] + g_boff[rel][b];
        g_off[rel][i + 1] = o;
        g_cursor[rel][i] = o - g_degd[rel][i];
    }
    if (i == 0) g_off[rel][0] = 0;
}

// ---------------- bucket edges by dst ----------------
__global__ void k_fill(const int* __restrict__ e0, const int* __restrict__ e1) {
    int rel = blockIdx.y;
    const int* edge = rel ? e1 : e0;
    int e = blockIdx.x * blockDim.x + threadIdx.x;
    if (e < EE) {
        int row = edge[e];
        int col = edge[EE + e];
        int pos = atomicAdd(&g_cursor[rel][col], 1);
        g_srt[rel][pos] = row;
    }
}

// ---------------- GEMM: xw = (x @ W) * inv_s  (both rels) ----------------
#define RLP 65
#define GEMM_SH_FLOATS (128 * 128 + 128 * RLP)
#define GEMM_SH_BYTES  (GEMM_SH_FLOATS * 4)

__global__ void __launch_bounds__(256) k_gemm(const float* __restrict__ x0,
                                              const float* __restrict__ x1) {
    extern __shared__ float sh[];
    __shared__ float sscale[64];
    int rel = blockIdx.y;
    const float* x = rel ? x1 : x0;
    float* Ws  = sh;                 // [c*128 + j]
    float* XsT = sh + 128 * 128;     // [c*RLP + r]
    int t = threadIdx.x;
    const float* W = g_W[rel];
    for (int i = t; i < 128 * 128; i += 256) Ws[i] = W[i];
    size_t rowbase = (size_t)blockIdx.x * 64;
    const float4* x4 = (const float4*)(x + rowbase * CC);
    #pragma unroll
    for (int k = 0; k < 8; k++) {
        int idx = t + k * 256;
        int row = idx >> 5;
        int c4  = idx & 31;
        float4 v = x4[(size_t)row * 32 + c4];
        XsT[(c4 * 4 + 0) * RLP + row] = v.x;
        XsT[(c4 * 4 + 1) * RLP + row] = v.y;
        XsT[(c4 * 4 + 2) * RLP + row] = v.z;
        XsT[(c4 * 4 + 3) * RLP + row] = v.w;
    }
    if (t < 64) {
        int d = g_degs[rel][rowbase + t];
        sscale[t] = (d > 0) ? rsqrtf((float)d) : 0.f;
    }
    __syncthreads();
    int lane = t & 31;
    int cg = t >> 5;
    int colbase = cg * 16;
    float acc0[16], acc1[16];
    #pragma unroll
    for (int i = 0; i < 16; i++) { acc0[i] = 0.f; acc1[i] = 0.f; }
    #pragma unroll 4
    for (int c = 0; c < 128; c++) {
        float xa = XsT[c * RLP + lane];
        float xb = XsT[c * RLP + lane + 32];
        const float4* wr = (const float4*)(Ws + c * 128 + colbase);
        float4 w0 = wr[0], w1 = wr[1], w2 = wr[2], w3 = wr[3];
        float wv[16] = { w0.x, w0.y, w0.z, w0.w, w1.x, w1.y, w1.z, w1.w,
                         w2.x, w2.y, w2.z, w2.w, w3.x, w3.y, w3.z, w3.w };
        #pragma unroll
        for (int i = 0; i < 16; i++) { acc0[i] += xa * wv[i]; acc1[i] += xb * wv[i]; }
    }
    __syncthreads();
    float* buf = sh;             // 64 x 129 staging
    #pragma unroll
    for (int i = 0; i < 16; i++) {
        buf[lane * 129 + colbase + i]        = acc0[i];
        buf[(lane + 32) * 129 + colbase + i] = acc1[i];
    }
    __syncthreads();
    float* out = g_xw[rel] + rowbase * CC;
    for (int e = t; e < 2048; e += 256) {
        int row = e >> 5, q = e & 31;
        float sc = sscale[row];
        float4 v = make_float4(buf[row * 129 + q * 4 + 0] * sc,
                               buf[row * 129 + q * 4 + 1] * sc,
                               buf[row * 129 + q * 4 + 2] * sc,
                               buf[row * 129 + q * 4 + 3] * sc);
        ((float4*)out)[e] = v;
    }
}

// ---------------- CSR aggregate: warp per dst node, relu fused ----------------
__global__ void k_agg() {
    int rel = blockIdx.y;
    int gw = (blockIdx.x * blockDim.x + threadIdx.x) >> 5;
    int lane = threadIdx.x & 31;
    if (gw >= NN) return;
    int start = g_off[rel][gw];
    int end   = g_off[rel][gw + 1];
    const float4* xw = (const float4*)g_xw[rel];
    const int* srt = g_srt[rel];
    float4 acc = make_float4(0.f, 0.f, 0.f, 0.f);
    for (int base = start; base < end; base += 32) {
        int n = min(32, end - base);
        int r = (base + lane < end) ? srt[base + lane] : 0;
        for (int k = 0; k < n; k++) {
            int row = __shfl_sync(0xffffffffu, r, k);
            float4 v = xw[(size_t)row * 32 + lane];
            acc.x += v.x; acc.y += v.y; acc.z += v.z; acc.w += v.w;
        }
    }
    int d = end - start;
    float s = (d > 0) ? rsqrtf((float)d) : 0.f;
    float4 o = make_float4(fmaxf(acc.x * s, 0.f), fmaxf(acc.y * s, 0.f),
                           fmaxf(acc.z * s, 0.f), fmaxf(acc.w * s, 0.f));
    ((float4*)g_h[rel])[(size_t)gw * 32 + lane] = o;
}

// ---------------- link scorer (h already relu'd) ----------------
__global__ void k_link(const int* __restrict__ eli, const float* __restrict__ Wp,
                       const float* __restrict__ bp, float* __restrict__ out) {
    __shared__ __align__(16) float swsum[CC];
    __shared__ float sb;
    int t = threadIdx.x;
    if (t < CC) swsum[t] = Wp[2 * t] + Wp[2 * t + 1];
    if (t == 0) sb = bp[0] + bp[1];
    __syncthreads();
    int gw = (blockIdx.x * blockDim.x + t) >> 5;
    int lane = t & 31;
    if (gw >= LL) return;
    int s = eli[gw], d = eli[LL + gw];
    const float4* hu = (const float4*)(g_h[1] + (size_t)s * CC);
    const float4* hi = (const float4*)(g_h[0] + (size_t)d * CC);
    float4 a = hu[lane], b = hi[lane];
    float4 w = ((const float4*)swsum)[lane];
    float acc = a.x * b.x * w.x + a.y * b.y * w.y + a.z * b.z * w.z + a.w * b.w * w.w;
    #pragma unroll
    for (int o = 16; o > 0; o >>= 1) acc += __shfl_down_sync(0xffffffffu, acc, o);
    if (lane == 0) out[gw] = acc + sb;
}

// ---------------- host launcher ----------------
extern "C" void kernel_launch(void* const* d_in, const int* in_sizes, int n_in,
                              void* d_out, int out_size) {
    (void)in_sizes; (void)n_in; (void)out_size;

    void *ph, *pds, *pdd;
    cudaGetSymbolAddress(&ph,  g_hist);
    cudaGetSymbolAddress(&pds, g_degs);
    cudaGetSymbolAddress(&pdd, g_degd);
    cudaMemsetAsync(ph,  0, sizeof(int) * 2 * NBIN, 0);
    cudaMemsetAsync(pds, 0, sizeof(int) * 2 * NN, 0);
    cudaMemsetAsync(pdd, 0, sizeof(int) * 2 * NN, 0);

    cudaFuncSetAttribute(k_gemm,  cudaFuncAttributeMaxDynamicSharedMemorySize, GEMM_SH_BYTES);
    cudaFuncSetAttribute(k_grumm, cudaFuncAttributeMaxDynamicSharedMemorySize, GRUMM_SH_BYTES);

    const float* x0 = (const float*)d_in[0];
    const float* x1 = (const float*)d_in[1];
    const int*   e0 = (const int*)d_in[2];
    const int*   e1 = (const int*)d_in[3];

    RelParams r0 = { (const float*)d_in[6],  (const float*)d_in[7],
                     (const float*)d_in[8],  (const float*)d_in[9],
                     (const float*)d_in[10] };
    RelParams r1 = { (const float*)d_in[12], (const float*)d_in[13],
                     (const float*)d_in[14], (const float*)d_in[15],
                     (const float*)d_in[16] };

    dim3 gScore((NN * 32 + 255) / 256, 2);
    k_score<<<gScore, 256>>>(x0, x1, (const float*)d_in[5], (const float*)d_in[11]);

    dim3 gDeg((EE + 255) / 256, 2);
    k_deg<<<gDeg, 256>>>(e0, e1);

    k_select<<<2, 1024>>>(x0, x1);
    k_grumm<<<dim3(6, 2, 2), 256, GRUMM_SH_BYTES>>>(r0, r1);
    k_gate<<<dim3(CC, 2), CC>>>(r0, r1);

    k_scan1<<<dim3(SCAN_BLK, 2), 1024>>>();
    k_scan2<<<2, 128>>>();
    k_scan3<<<dim3(SCAN_BLK, 2), 1024>>>();
    k_fill<<<gDeg, 256>>>(e0, e1);

    k_gemm<<<dim3(NN / 64, 2), 256, GEMM_SH_BYTES>>>(x0, x1);

    dim3 gAgg((NN * 32 + 255) / 256, 2);
    k_agg<<<gAgg, 256>>>();

    k_link<<<(LL * 32 + 255) / 256, 256>>>((const int*)d_in[4],
                                           (const float*)d_in[17],
                                           (const float*)d_in[18],
                                           (float*)d_out);
}

// round 4
// speedup vs baseline: 2.0220x; 1.1203x over previous
#include <cuda_runtime.h>
#include <math.h>

#define CC 128
#define NN 80000
#define EE 1000000
#define LL 400000
#define NBIN 4096
#define CAND_CAP 4096
#define SCAN_BLK 79     // ceil(80000/1024)
#define NPAD 80128      // 313 * 256
#define GEMM_BLKS 313

// ---------------- device scratch (static, no allocs) ----------------
__device__ float g_score[2][NN];
__device__ int   g_hist[2][NBIN];
__device__ float g_Xt[2][CC * CC];
__device__ float g_gip[2][2][4][CC * 3 * CC];   // [rel][src][kslice]
__device__ float g_W[2][CC * CC];
__device__ unsigned int g_Wfrag[2][32768];      // fragged W: hi/lo tf32
__device__ float g_xw[2][(size_t)NPAD * CC];    // pre-scaled by inv_s
__device__ int   g_degs[2][NN];
__device__ int   g_degd[2][NN];
__device__ int   g_off[2][NN + 1];
__device__ int   g_cursor[2][NN];
__device__ int   g_bsum[2][128];
__device__ int   g_boff[2][128];
__device__ int   g_srt[2][EE];
__device__ float g_h[2][(size_t)NN * CC];

struct RelParams {
    const float* W0; const float* Wih; const float* Whh;
    const float* bih; const float* bhh;
};

__device__ __forceinline__ unsigned int ordkey(float f) {
    unsigned int u = __float_as_uint(f);
    return (u & 0x80000000u) ? ~u : (u | 0x80000000u);
}
__device__ __forceinline__ float ordval(unsigned int u) {
    u = (u & 0x80000000u) ? (u & 0x7FFFFFFFu) : ~u;
    return __uint_as_float(u);
}
__device__ __forceinline__ unsigned int f2tf32(float f) {
    unsigned int u;
    asm("cvt.rna.tf32.f32 %0, %1;" : "=r"(u) : "f"(f));
    return u;
}
__device__ __forceinline__ void mma_tf32(float* d, const unsigned int* a,
                                         unsigned int b0, unsigned int b1) {
    asm volatile(
        "mma.sync.aligned.m16n8k8.row.col.f32.tf32.tf32.f32 "
        "{%0,%1,%2,%3},{%4,%5,%6,%7},{%8,%9},{%0,%1,%2,%3};"
        : "+f"(d[0]), "+f"(d[1]), "+f"(d[2]), "+f"(d[3])
        : "r"(a[0]), "r"(a[1]), "r"(a[2]), "r"(a[3]), "r"(b0), "r"(b1));
}

// ---------------- fused: score (blocks < 10000) + degree hist ----------------
__global__ void k_scoredeg(const float* __restrict__ x0, const float* __restrict__ x1,
                           const float* __restrict__ p0, const float* __restrict__ p1,
                           const int* __restrict__ e0, const int* __restrict__ e1) {
    int rel = blockIdx.y;
    int tid = threadIdx.x;
    if (blockIdx.x >= 10000) {
        const int* edge = rel ? e1 : e0;
        int e = (blockIdx.x - 10000) * 256 + tid;
        if (e < EE) {
            atomicAdd(&g_degs[rel][edge[e]], 1);
            atomicAdd(&g_degd[rel][edge[EE + e]], 1);
        }
        return;
    }
    const float* x = rel ? x1 : x0;
    const float* p = rel ? p1 : p0;
    __shared__ __align__(16) float sp[CC];
    __shared__ float snorm;
    if (tid < CC) sp[tid] = p[tid];
    __syncthreads();
    if (tid == 0) {
        float s = 0.f;
        for (int i = 0; i < CC; i++) s += sp[i] * sp[i];
        snorm = sqrtf(s) + 1e-16f;
    }
    __syncthreads();
    int lane = tid & 31;
    int gw = (blockIdx.x * 256 + tid) >> 5;
    if (gw < NN) {
        const float4* x4 = (const float4*)(x + (size_t)gw * CC);
        float4 xv = x4[lane];
        float4 pv = ((const float4*)sp)[lane];
        float d = xv.x * pv.x + xv.y * pv.y + xv.z * pv.z + xv.w * pv.w;
        #pragma unroll
        for (int o = 16; o > 0; o >>= 1) d += __shfl_down_sync(0xffffffffu, d, o);
        if (lane == 0) {
            float sc = d / snorm;
            g_score[rel][gw] = sc;
            atomicAdd(&g_hist[rel][ordkey(sc) >> 20], 1);
        }
    }
}

// ---------------- fused: threshold + collect + rank-select + X_tilde ----------------
__global__ void k_select(const float* __restrict__ x0, const float* __restrict__ x1) {
    int rel = blockIdx.x;
    const float* x = rel ? x1 : x0;
    __shared__ int s[1024];
    __shared__ int sB, scnt;
    __shared__ unsigned long long cand[CAND_CAP];
    __shared__ int   sidx[CC];
    __shared__ float sgate[CC];
    int t = threadIdx.x;
    const int* h = g_hist[rel];
    int b4 = t * 4;
    int v = h[b4] + h[b4 + 1] + h[b4 + 2] + h[b4 + 3];
    if (t == 0) scnt = 0;
    s[t] = v;
    __syncthreads();
    for (int off = 1; off < 1024; off <<= 1) {
        int u = (t + off < 1024) ? s[t + off] : 0;
        __syncthreads();
        s[t] += u;
        __syncthreads();
    }
    int snext = (t < 1023) ? s[t + 1] : 0;
    if (s[t] >= CC && snext < CC) {
        int acc = snext;
        int B = b4;
        for (int b = b4 + 3; b >= b4; b--) {
            acc += h[b];
            if (acc >= CC) { B = b; break; }
        }
        sB = B;
    }
    __syncthreads();
    int B = sB;
    for (int i = t; i < NN; i += 1024) {
        unsigned int k = ordkey(g_score[rel][i]);
        if ((int)(k >> 20) >= B) {
            int pos = atomicAdd(&scnt, 1);
            if (pos < CAND_CAP)
                cand[pos] = ((unsigned long long)k << 32)
                          | (unsigned long long)(0xFFFFFFFFu - (unsigned int)i);
        }
    }
    __syncthreads();
    int c = min(scnt, CAND_CAP);
    for (int i = t; i < c; i += 1024) {
        unsigned long long ki = cand[i];
        int r = 0;
        for (int j = 0; j < c; j++) r += (cand[j] > ki);
        if (r < CC) {
            sidx[r]  = (int)(0xFFFFFFFFu - (unsigned int)(ki & 0xFFFFFFFFu));
            sgate[r] = tanhf(ordval((unsigned int)(ki >> 32)));
        }
    }
    __syncthreads();
    for (int e = t; e < CC * CC; e += 1024) {
        int r = e >> 7, col = e & 127;
        g_Xt[rel][e] = x[(size_t)sidx[r] * CC + col] * sgate[r];
    }
}

// ---------------- GRU GEMMs, K-split 4: partial gi/gh ----------------
// grid (6, 2, 8): x = 64-col tile, y = rel, z = src*4 + kslice
__global__ void __launch_bounds__(256) k_grumm(RelParams r0, RelParams r1) {
    __shared__ float Ast[32 * 132];   // [c*132 + i]
    __shared__ float Ms[32 * 68];     // [c*68 + jl]
    int rel = blockIdx.y;
    int src = blockIdx.z >> 2;
    int ks  = blockIdx.z & 3;
    int bx  = blockIdx.x;
    RelParams rp = rel ? r1 : r0;
    const float* A = src ? rp.W0 : g_Xt[rel];
    const float* M = (src ? rp.Whh : rp.Wih) + (size_t)bx * 64 * 128;
    float* out = g_gip[rel][src][ks];
    int t = threadIdx.x;
    int kbase = ks * 32;
    for (int idx = t; idx < 128 * 32; idx += 256) {
        int i = idx >> 5, c = idx & 31;
        Ast[c * 132 + i] = A[i * 128 + kbase + c];
    }
    for (int idx = t; idx < 64 * 32; idx += 256) {
        int jl = idx >> 5, c = idx & 31;
        Ms[c * 68 + jl] = M[jl * 128 + kbase + c];
    }
    __syncthreads();
    int tx = t & 15;        // col group of 4
    int ty = t >> 4;        // row group of 8
    float acc[8][4];
    #pragma unroll
    for (int i = 0; i < 8; i++)
        #pragma unroll
        for (int j = 0; j < 4; j++) acc[i][j] = 0.f;
    #pragma unroll 2
    for (int k = 0; k < 32; k++) {
        float4 a0 = *(const float4*)&Ast[k * 132 + ty * 8];
        float4 a1 = *(const float4*)&Ast[k * 132 + ty * 8 + 4];
        float4 b  = *(const float4*)&Ms[k * 68 + tx * 4];
        float av[8] = { a0.x, a0.y, a0.z, a0.w, a1.x, a1.y, a1.z, a1.w };
        #pragma unroll
        for (int i = 0; i < 8; i++) {
            acc[i][0] += av[i] * b.x;
            acc[i][1] += av[i] * b.y;
            acc[i][2] += av[i] * b.z;
            acc[i][3] += av[i] * b.w;
        }
    }
    #pragma unroll
    for (int i = 0; i < 8; i++) {
        int row = ty * 8 + i;
        int col = bx * 64 + tx * 4;
        *(float4*)&out[row * 384 + col] =
            make_float4(acc[i][0], acc[i][1], acc[i][2], acc[i][3]);
    }
}

// ---------------- GRU gates -> evolved W (sums 4 K-partials) ----------------
__global__ void k_gate(RelParams r0, RelParams r1) {
    int rel = blockIdx.y;
    RelParams rp = rel ? r1 : r0;
    int i = blockIdx.x;
    int t = threadIdx.x;
    float ir = 0.f, iz = 0.f, in2 = 0.f, hr = 0.f, hz = 0.f, hn = 0.f;
    #pragma unroll
    for (int s = 0; s < 4; s++) {
        const float* pi = g_gip[rel][0][s] + i * 384;
        const float* ph = g_gip[rel][1][s] + i * 384;
        ir += pi[t]; iz += pi[t + 128]; in2 += pi[t + 256];
        hr += ph[t]; hz += ph[t + 128]; hn += ph[t + 256];
    }
    ir += rp.bih[t]; iz += rp.bih[t + 128]; in2 += rp.bih[t + 256];
    hr += rp.bhh[t]; hz += rp.bhh[t + 128]; hn += rp.bhh[t + 256];
    float w0 = rp.W0[i * CC + t];
    float r = 1.f / (1.f + expf(-(ir + hr)));
    float z = 1.f / (1.f + expf(-(iz + hz)));
    float n = tanhf(in2 + r * hn);
    g_W[rel][i * CC + t] = (1.f - z) * n + z * w0;
}

// ---------------- pre-fragment W into mma layout (hi/lo tf32) ----------------
__global__ void k_wfrag() {
    int rel = blockIdx.x;
    int t = threadIdx.x;
    const float* W = g_W[rel];
    for (int e = t; e < 8192; e += 1024) {
        int kstep = e >> 9, nt = (e >> 5) & 15, lane = e & 31;
        int tg = lane & 3, g = lane >> 2;
        int k0 = kstep * 8 + tg, col = nt * 8 + g;
        float w0 = W[k0 * 128 + col];
        float w1 = W[(k0 + 4) * 128 + col];
        unsigned int h0 = f2tf32(w0), h1 = f2tf32(w1);
        unsigned int l0 = f2tf32(w0 - __uint_as_float(h0));
        unsigned int l1 = f2tf32(w1 - __uint_as_float(h1));
        ((uint4*)g_Wfrag[rel])[e] = make_uint4(h0, h1, l0, l1);
    }
}

// ---------------- hierarchical scan of degd ----------------
__global__ void k_scan1() {
    int rel = blockIdx.y, b = blockIdx.x;
    __shared__ int wsum[32];
    int t = threadIdx.x, lane = t & 31, w = t >> 5;
    int i = b * 1024 + t;
    int v = (i < NN) ? g_degd[rel][i] : 0;
    int inc = v;
    #pragma unroll
    for (int off = 1; off < 32; off <<= 1) {
        int u = __shfl_up_sync(0xffffffffu, inc, off);
        if (lane >= off) inc += u;
    }
    if (lane == 31) wsum[w] = inc;
    __syncthreads();
    if (w == 0) {
        int xv = wsum[lane];
        int ws = xv;
        #pragma unroll
        for (int off = 1; off < 32; off <<= 1) {
            int u = __shfl_up_sync(0xffffffffu, ws, off);
            if (lane >= off) ws += u;
        }
        wsum[lane] = ws - xv;
    }
    __syncthreads();
    int incl = inc + wsum[w];
    if (i < NN) g_off[rel][i + 1] = incl;
    if (t == 1023) g_bsum[rel][b] = incl;
}

__global__ void k_scan2() {
    int rel = blockIdx.x;
    __shared__ int s[SCAN_BLK];
    int t = threadIdx.x;
    if (t < SCAN_BLK) s[t] = g_bsum[rel][t];
    __syncthreads();
    if (t == 0) {
        int acc = 0;
        for (int b = 0; b < SCAN_BLK; b++) {
            g_boff[rel][b] = acc;
            acc += s[b];
        }
    }
}

__global__ void k_scan3() {
    int rel = blockIdx.y, b = blockIdx.x;
    int t = threadIdx.x;
    int i = b * 1024 + t;
    if (i < NN) {
        int o = g_off[rel][i + 1] + g_boff[rel][b];
        g_off[rel][i + 1] = o;
        g_cursor[rel][i] = o - g_degd[rel][i];
    }
    if (i == 0) g_off[rel][0] = 0;
}

// ---------------- bucket edges by dst ----------------
__global__ void k_fill(const int* __restrict__ e0, const int* __restrict__ e1) {
    int rel = blockIdx.y;
    const int* edge = rel ? e1 : e0;
    int e = blockIdx.x * blockDim.x + threadIdx.x;
    if (e < EE) {
        int row = edge[e];
        int col = edge[EE + e];
        int pos = atomicAdd(&g_cursor[rel][col], 1);
        g_srt[rel][pos] = row;
    }
}

// ---------------- GEMM: xw = (x @ W) * inv_s  via tf32 mma, 3-pass split ----------------
__global__ void __launch_bounds__(256, 1) k_gemm_tf32(const float* __restrict__ x0,
                                                      const float* __restrict__ x1) {
    extern __shared__ uint4 shW[];       // 8192 uint4 = 128 KB
    __shared__ float sscale[256];
    int rel = blockIdx.y;
    const float* __restrict__ x = rel ? x1 : x0;
    int t = threadIdx.x;
    const uint4* Wf = (const uint4*)g_Wfrag[rel];
    for (int i = t; i < 8192; i += 256) shW[i] = Wf[i];
    int rblk = blockIdx.x * 256;
    {
        int rc = min(rblk + t, NN - 1);
        int dg = g_degs[rel][rc];
        sscale[t] = (dg > 0) ? rsqrtf((float)dg) : 0.f;
    }
    __syncthreads();
    int lane = t & 31, w = t >> 5, tg = lane & 3, g = lane >> 2;
    float D[2][16][4];
    #pragma unroll
    for (int m = 0; m < 2; m++)
        #pragma unroll
        for (int nt = 0; nt < 16; nt++)
            #pragma unroll
            for (int j = 0; j < 4; j++) D[m][nt][j] = 0.f;

    size_t ra[2], rb[2];
    #pragma unroll
    for (int m = 0; m < 2; m++) {
        int rl = w * 32 + m * 16 + g;
        ra[m] = (size_t)min(rblk + rl, NN - 1) * 128;
        rb[m] = (size_t)min(rblk + rl + 8, NN - 1) * 128;
    }

    for (int kstep = 0; kstep < 16; kstep++) {
        int c0 = kstep * 8 + tg;
        unsigned int ah[2][4], al[2][4];
        #pragma unroll
        for (int m = 0; m < 2; m++) {
            float f0 = __ldg(x + ra[m] + c0);
            float f1 = __ldg(x + rb[m] + c0);
            float f2 = __ldg(x + ra[m] + c0 + 4);
            float f3 = __ldg(x + rb[m] + c0 + 4);
            ah[m][0] = f2tf32(f0); al[m][0] = f2tf32(f0 - __uint_as_float(ah[m][0]));
            ah[m][1] = f2tf32(f1); al[m][1] = f2tf32(f1 - __uint_as_float(ah[m][1]));
            ah[m][2] = f2tf32(f2); al[m][2] = f2tf32(f2 - __uint_as_float(ah[m][2]));
            ah[m][3] = f2tf32(f3); al[m][3] = f2tf32(f3 - __uint_as_float(ah[m][3]));
        }
        const uint4* wk = shW + (kstep << 9);
        #pragma unroll
        for (int nt = 0; nt < 16; nt++) {
            uint4 b = wk[(nt << 5) + lane];
            #pragma unroll
            for (int m = 0; m < 2; m++) {
                mma_tf32(D[m][nt], ah[m], b.x, b.y);   // hi * hi
                mma_tf32(D[m][nt], ah[m], b.z, b.w);   // hi * lo
                mma_tf32(D[m][nt], al[m], b.x, b.y);   // lo * hi
            }
        }
    }

    float* out = g_xw[rel];
    #pragma unroll
    for (int m = 0; m < 2; m++) {
        int rl0 = w * 32 + m * 16 + g;
        float s0 = sscale[rl0], s1 = sscale[rl0 + 8];
        size_t row0 = (size_t)(rblk + rl0) * 128;
        size_t row1 = row0 + 8 * 128;
        #pragma unroll
        for (int nt = 0; nt < 16; nt++) {
            int col = (nt << 3) + tg * 2;
            *(float2*)(out + row0 + col) = make_float2(D[m][nt][0] * s0, D[m][nt][1] * s0);
            *(float2*)(out + row1 + col) = make_float2(D[m][nt][2] * s1, D[m][nt][3] * s1);
        }
    }
}

// ---------------- CSR aggregate: warp per dst node, relu fused ----------------
__global__ void k_agg() {
    int rel = blockIdx.y;
    int gw = (blockIdx.x * blockDim.x + threadIdx.x) >> 5;
    int lane = threadIdx.x & 31;
    if (gw >= NN) return;
    int start = g_off[rel][gw];
    int end   = g_off[rel][gw + 1];
    const float4* xw = (const float4*)g_xw[rel];
    const int* srt = g_srt[rel];
    float4 acc = make_float4(0.f, 0.f, 0.f, 0.f);
    for (int base = start; base < end; base += 32) {
        int n = min(32, end - base);
        int r = (base + lane < end) ? srt[base + lane] : 0;
        for (int k = 0; k < n; k++) {
            int row = __shfl_sync(0xffffffffu, r, k);
            float4 v = xw[(size_t)row * 32 + lane];
            acc.x += v.x; acc.y += v.y; acc.z += v.z; acc.w += v.w;
        }
    }
    int d = end - start;
    float s = (d > 0) ? rsqrtf((float)d) : 0.f;
    float4 o = make_float4(fmaxf(acc.x * s, 0.f), fmaxf(acc.y * s, 0.f),
                           fmaxf(acc.z * s, 0.f), fmaxf(acc.w * s, 0.f));
    ((float4*)g_h[rel])[(size_t)gw * 32 + lane] = o;
}

// ---------------- link scorer (h already relu'd) ----------------
__global__ void k_link(const int* __restrict__ eli, const float* __restrict__ Wp,
                       const float* __restrict__ bp, float* __restrict__ out) {
    __shared__ __align__(16) float swsum[CC];
    __shared__ float sb;
    int t = threadIdx.x;
    if (t < CC) swsum[t] = Wp[2 * t] + Wp[2 * t + 1];
    if (t == 0) sb = bp[0] + bp[1];
    __syncthreads();
    int gw = (blockIdx.x * blockDim.x + t) >> 5;
    int lane = t & 31;
    if (gw >= LL) return;
    int s = eli[gw], d = eli[LL + gw];
    const float4* hu = (const float4*)(g_h[1] + (size_t)s * CC);
    const float4* hi = (const float4*)(g_h[0] + (size_t)d * CC);
    float4 a = hu[lane], b = hi[lane];
    float4 w = ((const float4*)swsum)[lane];
    float acc = a.x * b.x * w.x + a.y * b.y * w.y + a.z * b.z * w.z + a.w * b.w * w.w;
    #pragma unroll
    for (int o = 16; o > 0; o >>= 1) acc += __shfl_down_sync(0xffffffffu, acc, o);
    if (lane == 0) out[gw] = acc + sb;
}

// ---------------- host launcher ----------------
extern "C" void kernel_launch(void* const* d_in, const int* in_sizes, int n_in,
                              void* d_out, int out_size) {
    (void)in_sizes; (void)n_in; (void)out_size;

    void *ph, *pds, *pdd;
    cudaGetSymbolAddress(&ph,  g_hist);
    cudaGetSymbolAddress(&pds, g_degs);
    cudaGetSymbolAddress(&pdd, g_degd);
    cudaMemsetAsync(ph,  0, sizeof(int) * 2 * NBIN, 0);
    cudaMemsetAsync(pds, 0, sizeof(int) * 2 * NN, 0);
    cudaMemsetAsync(pdd, 0, sizeof(int) * 2 * NN, 0);

    cudaFuncSetAttribute(k_gemm_tf32, cudaFuncAttributeMaxDynamicSharedMemorySize, 131072);

    const float* x0 = (const float*)d_in[0];
    const float* x1 = (const float*)d_in[1];
    const int*   e0 = (const int*)d_in[2];
    const int*   e1 = (const int*)d_in[3];

    RelParams r0 = { (const float*)d_in[6],  (const float*)d_in[7],
                     (const float*)d_in[8],  (const float*)d_in[9],
                     (const float*)d_in[10] };
    RelParams r1 = { (const float*)d_in[12], (const float*)d_in[13],
                     (const float*)d_in[14], (const float*)d_in[15],
                     (const float*)d_in[16] };

    // score (10000 blocks) + degree hist (3907 blocks), both rels
    dim3 gSD(10000 + (EE + 255) / 256, 2);
    k_scoredeg<<<gSD, 256>>>(x0, x1, (const float*)d_in[5], (const float*)d_in[11], e0, e1);

    k_select<<<2, 1024>>>(x0, x1);
    k_grumm<<<dim3(6, 2, 8), 256>>>(r0, r1);
    k_gate<<<dim3(CC, 2), CC>>>(r0, r1);
    k_wfrag<<<2, 1024>>>();

    k_scan1<<<dim3(SCAN_BLK, 2), 1024>>>();
    k_scan2<<<2, 128>>>();
    k_scan3<<<dim3(SCAN_BLK, 2), 1024>>>();
    dim3 gFill((EE + 255) / 256, 2);
    k_fill<<<gFill, 256>>>(e0, e1);

    k_gemm_tf32<<<dim3(GEMM_BLKS, 2), 256, 131072>>>(x0, x1);

    dim3 gAgg((NN * 32 + 255) / 256, 2);
    k_agg<<<gAgg, 256>>>();

    k_link<<<(LL * 32 + 255) / 256, 256>>>((const int*)d_in[4],
                                           (const float*)d_in[17],
                                           (const float*)d_in[18],
                                           (float*)d_out);
}

// round 5
// speedup vs baseline: 2.1254x; 1.0511x over previous
#include <cuda_runtime.h>
#include <math.h>

#define CC 128
#define NN 80000
#define EE 1000000
#define LL 400000
#define NBIN 4096
#define CAND_CAP 4096
#define SCAN_BLK 79     // ceil(80000/1024)
#define NPAD 80128      // 313 * 256
#define GEMM_BLKS 313

// ---------------- device scratch (static, no allocs) ----------------
__device__ float g_score[2][NN];
__device__ int   g_hist[2][NBIN];
__device__ float g_Xt[2][CC * CC];
__device__ float g_gip[2][2][4][CC * 3 * CC];   // [rel][src][kslice]
__device__ float g_W[2][CC * CC];
__device__ float g_xw[2][(size_t)NPAD * CC];    // pre-scaled by inv_s
__device__ int   g_degs[2][NN];
__device__ int   g_degd[2][NN];
__device__ int   g_off[2][NN + 1];
__device__ int   g_cursor[2][NN];
__device__ int   g_bsum[2][128];
__device__ int   g_srt[2][EE];
__device__ float g_h[2][(size_t)NN * CC];

struct RelParams {
    const float* W0; const float* Wih; const float* Whh;
    const float* bih; const float* bhh;
};

__device__ __forceinline__ unsigned int ordkey(float f) {
    unsigned int u = __float_as_uint(f);
    return (u & 0x80000000u) ? ~u : (u | 0x80000000u);
}
__device__ __forceinline__ float ordval(unsigned int u) {
    u = (u & 0x80000000u) ? (u & 0x7FFFFFFFu) : ~u;
    return __uint_as_float(u);
}
__device__ __forceinline__ unsigned int f2tf32(float f) {
    unsigned int u;
    asm("cvt.rna.tf32.f32 %0, %1;" : "=r"(u) : "f"(f));
    return u;
}
__device__ __forceinline__ void mma_tf32(float* d, const unsigned int* a,
                                         unsigned int b0, unsigned int b1) {
    asm volatile(
        "mma.sync.aligned.m16n8k8.row.col.f32.tf32.tf32.f32 "
        "{%0,%1,%2,%3},{%4,%5,%6,%7},{%8,%9},{%0,%1,%2,%3};"
        : "+f"(d[0]), "+f"(d[1]), "+f"(d[2]), "+f"(d[3])
        : "r"(a[0]), "r"(a[1]), "r"(a[2]), "r"(a[3]), "r"(b0), "r"(b1));
}

// ---------------- fused: score (blocks < 10000) + degree hist ----------------
__global__ void k_scoredeg(const float* __restrict__ x0, const float* __restrict__ x1,
                           const float* __restrict__ p0, const float* __restrict__ p1,
                           const int* __restrict__ e0, const int* __restrict__ e1) {
    int rel = blockIdx.y;
    int tid = threadIdx.x;
    if (blockIdx.x >= 10000) {
        const int* edge = rel ? e1 : e0;
        int e = (blockIdx.x - 10000) * 256 + tid;
        if (e < EE) {
            atomicAdd(&g_degs[rel][edge[e]], 1);
            atomicAdd(&g_degd[rel][edge[EE + e]], 1);
        }
        return;
    }
    const float* x = rel ? x1 : x0;
    const float* p = rel ? p1 : p0;
    __shared__ __align__(16) float sp[CC];
    __shared__ float snorm;
    if (tid < CC) sp[tid] = p[tid];
    __syncthreads();
    if (tid == 0) {
        float s = 0.f;
        for (int i = 0; i < CC; i++) s += sp[i] * sp[i];
        snorm = sqrtf(s) + 1e-16f;
    }
    __syncthreads();
    int lane = tid & 31;
    int gw = (blockIdx.x * 256 + tid) >> 5;
    if (gw < NN) {
        const float4* x4 = (const float4*)(x + (size_t)gw * CC);
        float4 xv = x4[lane];
        float4 pv = ((const float4*)sp)[lane];
        float d = xv.x * pv.x + xv.y * pv.y + xv.z * pv.z + xv.w * pv.w;
        #pragma unroll
        for (int o = 16; o > 0; o >>= 1) d += __shfl_down_sync(0xffffffffu, d, o);
        if (lane == 0) {
            float sc = d / snorm;
            g_score[rel][gw] = sc;
            atomicAdd(&g_hist[rel][ordkey(sc) >> 20], 1);
        }
    }
}

// ---------------- fused: threshold + collect + rank-select + X_tilde ----------------
__global__ void k_select(const float* __restrict__ x0, const float* __restrict__ x1) {
    int rel = blockIdx.x;
    const float* x = rel ? x1 : x0;
    __shared__ int s[1024];
    __shared__ int sB, scnt;
    __shared__ unsigned long long cand[CAND_CAP];
    __shared__ int   sidx[CC];
    __shared__ float sgate[CC];
    int t = threadIdx.x;
    const int* h = g_hist[rel];
    int b4 = t * 4;
    int v = h[b4] + h[b4 + 1] + h[b4 + 2] + h[b4 + 3];
    if (t == 0) scnt = 0;
    s[t] = v;
    __syncthreads();
    for (int off = 1; off < 1024; off <<= 1) {
        int u = (t + off < 1024) ? s[t + off] : 0;
        __syncthreads();
        s[t] += u;
        __syncthreads();
    }
    int snext = (t < 1023) ? s[t + 1] : 0;
    if (s[t] >= CC && snext < CC) {
        int acc = snext;
        int B = b4;
        for (int b = b4 + 3; b >= b4; b--) {
            acc += h[b];
            if (acc >= CC) { B = b; break; }
        }
        sB = B;
    }
    __syncthreads();
    int B = sB;
    for (int i = t; i < NN; i += 1024) {
        unsigned int k = ordkey(g_score[rel][i]);
        if ((int)(k >> 20) >= B) {
            int pos = atomicAdd(&scnt, 1);
            if (pos < CAND_CAP)
                cand[pos] = ((unsigned long long)k << 32)
                          | (unsigned long long)(0xFFFFFFFFu - (unsigned int)i);
        }
    }
    __syncthreads();
    int c = min(scnt, CAND_CAP);
    for (int i = t; i < c; i += 1024) {
        unsigned long long ki = cand[i];
        int r = 0;
        for (int j = 0; j < c; j++) r += (cand[j] > ki);
        if (r < CC) {
            sidx[r]  = (int)(0xFFFFFFFFu - (unsigned int)(ki & 0xFFFFFFFFu));
            sgate[r] = tanhf(ordval((unsigned int)(ki >> 32)));
        }
    }
    __syncthreads();
    for (int e = t; e < CC * CC; e += 1024) {
        int r = e >> 7, col = e & 127;
        g_Xt[rel][e] = x[(size_t)sidx[r] * CC + col] * sgate[r];
    }
}

// ---------------- GRU GEMMs, K-split 4: partial gi/gh ----------------
__global__ void __launch_bounds__(256) k_grumm(RelParams r0, RelParams r1) {
    __shared__ float Ast[32 * 132];
    __shared__ float Ms[32 * 68];
    int rel = blockIdx.y;
    int src = blockIdx.z >> 2;
    int ks  = blockIdx.z & 3;
    int bx  = blockIdx.x;
    RelParams rp = rel ? r1 : r0;
    const float* A = src ? rp.W0 : g_Xt[rel];
    const float* M = (src ? rp.Whh : rp.Wih) + (size_t)bx * 64 * 128;
    float* out = g_gip[rel][src][ks];
    int t = threadIdx.x;
    int kbase = ks * 32;
    for (int idx = t; idx < 128 * 32; idx += 256) {
        int i = idx >> 5, c = idx & 31;
        Ast[c * 132 + i] = A[i * 128 + kbase + c];
    }
    for (int idx = t; idx < 64 * 32; idx += 256) {
        int jl = idx >> 5, c = idx & 31;
        Ms[c * 68 + jl] = M[jl * 128 + kbase + c];
    }
    __syncthreads();
    int tx = t & 15;
    int ty = t >> 4;
    float acc[8][4];
    #pragma unroll
    for (int i = 0; i < 8; i++)
        #pragma unroll
        for (int j = 0; j < 4; j++) acc[i][j] = 0.f;
    #pragma unroll 2
    for (int k = 0; k < 32; k++) {
        float4 a0 = *(const float4*)&Ast[k * 132 + ty * 8];
        float4 a1 = *(const float4*)&Ast[k * 132 + ty * 8 + 4];
        float4 b  = *(const float4*)&Ms[k * 68 + tx * 4];
        float av[8] = { a0.x, a0.y, a0.z, a0.w, a1.x, a1.y, a1.z, a1.w };
        #pragma unroll
        for (int i = 0; i < 8; i++) {
            acc[i][0] += av[i] * b.x;
            acc[i][1] += av[i] * b.y;
            acc[i][2] += av[i] * b.z;
            acc[i][3] += av[i] * b.w;
        }
    }
    #pragma unroll
    for (int i = 0; i < 8; i++) {
        int row = ty * 8 + i;
        int col = bx * 64 + tx * 4;
        *(float4*)&out[row * 384 + col] =
            make_float4(acc[i][0], acc[i][1], acc[i][2], acc[i][3]);
    }
}

// ---------------- GRU gates -> evolved W (sums 4 K-partials) ----------------
__global__ void k_gate(RelParams r0, RelParams r1) {
    int rel = blockIdx.y;
    RelParams rp = rel ? r1 : r0;
    int i = blockIdx.x;
    int t = threadIdx.x;
    float ir = 0.f, iz = 0.f, in2 = 0.f, hr = 0.f, hz = 0.f, hn = 0.f;
    #pragma unroll
    for (int s = 0; s < 4; s++) {
        const float* pi = g_gip[rel][0][s] + i * 384;
        const float* ph = g_gip[rel][1][s] + i * 384;
        ir += pi[t]; iz += pi[t + 128]; in2 += pi[t + 256];
        hr += ph[t]; hz += ph[t + 128]; hn += ph[t + 256];
    }
    ir += rp.bih[t]; iz += rp.bih[t + 128]; in2 += rp.bih[t + 256];
    hr += rp.bhh[t]; hz += rp.bhh[t + 128]; hn += rp.bhh[t + 256];
    float w0 = rp.W0[i * CC + t];
    float r = 1.f / (1.f + expf(-(ir + hr)));
    float z = 1.f / (1.f + expf(-(iz + hz)));
    float n = tanhf(in2 + r * hn);
    g_W[rel][i * CC + t] = (1.f - z) * n + z * w0;
}

// ---------------- hierarchical scan of degd ----------------
__global__ void k_scan1() {
    int rel = blockIdx.y, b = blockIdx.x;
    __shared__ int wsum[32];
    int t = threadIdx.x, lane = t & 31, w = t >> 5;
    int i = b * 1024 + t;
    int v = (i < NN) ? g_degd[rel][i] : 0;
    int inc = v;
    #pragma unroll
    for (int off = 1; off < 32; off <<= 1) {
        int u = __shfl_up_sync(0xffffffffu, inc, off);
        if (lane >= off) inc += u;
    }
    if (lane == 31) wsum[w] = inc;
    __syncthreads();
    if (w == 0) {
        int xv = wsum[lane];
        int ws = xv;
        #pragma unroll
        for (int off = 1; off < 32; off <<= 1) {
            int u = __shfl_up_sync(0xffffffffu, ws, off);
            if (lane >= off) ws += u;
        }
        wsum[lane] = ws - xv;
    }
    __syncthreads();
    int incl = inc + wsum[w];
    if (i < NN) g_off[rel][i + 1] = incl;
    if (t == 1023) g_bsum[rel][b] = incl;
}

// scan3: each block computes its own offset by reducing bsum[0..b-1]
__global__ void k_scan3() {
    int rel = blockIdx.y, b = blockIdx.x;
    int t = threadIdx.x, lane = t & 31, w = t >> 5;
    __shared__ int spart[4];
    __shared__ int sboff;
    if (t < 128) {
        int p = (t < b) ? g_bsum[rel][t] : 0;   // SCAN_BLK=79 < 128
        #pragma unroll
        for (int o = 16; o > 0; o >>= 1) p += __shfl_down_sync(0xffffffffu, p, o);
        if (lane == 0) spart[w] = p;
    }
    __syncthreads();
    if (t == 0) sboff = spart[0] + spart[1] + spart[2] + spart[3];
    __syncthreads();
    int i = b * 1024 + t;
    if (i < NN) {
        int o = g_off[rel][i + 1] + sboff;
        g_off[rel][i + 1] = o;
        g_cursor[rel][i] = o - g_degd[rel][i];
    }
    if (i == 0) g_off[rel][0] = 0;
}

// ---------------- bucket edges by dst ----------------
__global__ void k_fill(const int* __restrict__ e0, const int* __restrict__ e1) {
    int rel = blockIdx.y;
    const int* edge = rel ? e1 : e0;
    int e = blockIdx.x * blockDim.x + threadIdx.x;
    if (e < EE) {
        int row = edge[e];
        int col = edge[EE + e];
        int pos = atomicAdd(&g_cursor[rel][col], 1);
        g_srt[rel][pos] = row;
    }
}

// ---------------- GEMM: xw = (x @ W) * inv_s, tf32 mma 3-pass, prefetched ----------------
__global__ void __launch_bounds__(256, 1) k_gemm_tf32(const float* __restrict__ x0,
                                                      const float* __restrict__ x1) {
    extern __shared__ uint4 shW[];       // 8192 uint4 = 128 KB
    __shared__ float sscale[256];
    int rel = blockIdx.y;
    const float* __restrict__ x = rel ? x1 : x0;
    int t = threadIdx.x;
    // build W fragment in smem from g_W (hi/lo tf32 split)
    const float* W = g_W[rel];
    for (int e = t; e < 8192; e += 256) {
        int kstep = e >> 9, nt = (e >> 5) & 15, ln = e & 31;
        int tg0 = ln & 3, g0 = ln >> 2;
        int k0 = kstep * 8 + tg0, col = nt * 8 + g0;
        float w0 = W[k0 * 128 + col];
        float w1 = W[(k0 + 4) * 128 + col];
        unsigned int h0 = f2tf32(w0), h1 = f2tf32(w1);
        unsigned int l0 = f2tf32(w0 - __uint_as_float(h0));
        unsigned int l1 = f2tf32(w1 - __uint_as_float(h1));
        shW[e] = make_uint4(h0, h1, l0, l1);
    }
    int rblk = blockIdx.x * 256;
    {
        int rc = min(rblk + t, NN - 1);
        int dg = g_degs[rel][rc];
        sscale[t] = (dg > 0) ? rsqrtf((float)dg) : 0.f;
    }
    __syncthreads();
    int lane = t & 31, w = t >> 5, tg = lane & 3, g = lane >> 2;
    float D[2][16][4];
    #pragma unroll
    for (int m = 0; m < 2; m++)
        #pragma unroll
        for (int nt = 0; nt < 16; nt++)
            #pragma unroll
            for (int j = 0; j < 4; j++) D[m][nt][j] = 0.f;

    size_t ra0, rb0, ra1, rb1;
    {
        int rl0 = w * 32 + g;
        int rl1 = w * 32 + 16 + g;
        ra0 = (size_t)min(rblk + rl0, NN - 1) * 128;
        rb0 = (size_t)min(rblk + rl0 + 8, NN - 1) * 128;
        ra1 = (size_t)min(rblk + rl1, NN - 1) * 128;
        rb1 = (size_t)min(rblk + rl1 + 8, NN - 1) * 128;
    }

    float xf[8];
    {
        int c0 = tg;
        xf[0] = __ldg(x + ra0 + c0);     xf[1] = __ldg(x + rb0 + c0);
        xf[2] = __ldg(x + ra0 + c0 + 4); xf[3] = __ldg(x + rb0 + c0 + 4);
        xf[4] = __ldg(x + ra1 + c0);     xf[5] = __ldg(x + rb1 + c0);
        xf[6] = __ldg(x + ra1 + c0 + 4); xf[7] = __ldg(x + rb1 + c0 + 4);
    }

    #pragma unroll 2
    for (int kstep = 0; kstep < 16; kstep++) {
        float xn[8];
        if (kstep < 15) {
            int c0 = (kstep + 1) * 8 + tg;
            xn[0] = __ldg(x + ra0 + c0);     xn[1] = __ldg(x + rb0 + c0);
            xn[2] = __ldg(x + ra0 + c0 + 4); xn[3] = __ldg(x + rb0 + c0 + 4);
            xn[4] = __ldg(x + ra1 + c0);     xn[5] = __ldg(x + rb1 + c0);
            xn[6] = __ldg(x + ra1 + c0 + 4); xn[7] = __ldg(x + rb1 + c0 + 4);
        }
        unsigned int ah[2][4], al[2][4];
        #pragma unroll
        for (int m = 0; m < 2; m++) {
            #pragma unroll
            for (int j = 0; j < 4; j++) {
                float f = xf[m * 4 + j];
                ah[m][j] = f2tf32(f);
                al[m][j] = f2tf32(f - __uint_as_float(ah[m][j]));
            }
        }
        const uint4* wk = shW + (kstep << 9);
        #pragma unroll
        for (int nt = 0; nt < 16; nt++) {
            uint4 b = wk[(nt << 5) + lane];
            #pragma unroll
            for (int m = 0; m < 2; m++) {
                mma_tf32(D[m][nt], ah[m], b.x, b.y);   // hi * hi
                mma_tf32(D[m][nt], ah[m], b.z, b.w);   // hi * lo
                mma_tf32(D[m][nt], al[m], b.x, b.y);   // lo * hi
            }
        }
        #pragma unroll
        for (int j = 0; j < 8; j++) xf[j] = xn[j];
    }

    float* out = g_xw[rel];
    #pragma unroll
    for (int m = 0; m < 2; m++) {
        int rl0 = w * 32 + m * 16 + g;
        float s0 = sscale[rl0], s1 = sscale[rl0 + 8];
        size_t row0 = (size_t)(rblk + rl0) * 128;
        size_t row1 = row0 + 8 * 128;
        #pragma unroll
        for (int nt = 0; nt < 16; nt++) {
            int col = (nt << 3) + tg * 2;
            *(float2*)(out + row0 + col) = make_float2(D[m][nt][0] * s0, D[m][nt][1] * s0);
            *(float2*)(out + row1 + col) = make_float2(D[m][nt][2] * s1, D[m][nt][3] * s1);
        }
    }
}

// ---------------- CSR aggregate: warp per dst node, 4-deep MLP, relu fused ----------------
__global__ void k_agg() {
    int rel = blockIdx.y;
    int gw = (blockIdx.x * blockDim.x + threadIdx.x) >> 5;
    int lane = threadIdx.x & 31;
    if (gw >= NN) return;
    int start = g_off[rel][gw];
    int end   = g_off[rel][gw + 1];
    const float4* xw = (const float4*)g_xw[rel];
    const int* srt = g_srt[rel];
    float4 acc = make_float4(0.f, 0.f, 0.f, 0.f);
    for (int base = start; base < end; base += 32) {
        int n = min(32, end - base);
        int r = (base + lane < end) ? srt[base + lane] : 0;
        int k = 0;
        for (; k + 4 <= n; k += 4) {
            int q0 = __shfl_sync(0xffffffffu, r, k);
            int q1 = __shfl_sync(0xffffffffu, r, k + 1);
            int q2 = __shfl_sync(0xffffffffu, r, k + 2);
            int q3 = __shfl_sync(0xffffffffu, r, k + 3);
            float4 v0 = xw[(size_t)q0 * 32 + lane];
            float4 v1 = xw[(size_t)q1 * 32 + lane];
            float4 v2 = xw[(size_t)q2 * 32 + lane];
            float4 v3 = xw[(size_t)q3 * 32 + lane];
            acc.x += (v0.x + v1.x) + (v2.x + v3.x);
            acc.y += (v0.y + v1.y) + (v2.y + v3.y);
            acc.z += (v0.z + v1.z) + (v2.z + v3.z);
            acc.w += (v0.w + v1.w) + (v2.w + v3.w);
        }
        for (; k < n; k++) {
            int q = __shfl_sync(0xffffffffu, r, k);
            float4 v = xw[(size_t)q * 32 + lane];
            acc.x += v.x; acc.y += v.y; acc.z += v.z; acc.w += v.w;
        }
    }
    int d = end - start;
    float s = (d > 0) ? rsqrtf((float)d) : 0.f;
    float4 o = make_float4(fmaxf(acc.x * s, 0.f), fmaxf(acc.y * s, 0.f),
                           fmaxf(acc.z * s, 0.f), fmaxf(acc.w * s, 0.f));
    ((float4*)g_h[rel])[(size_t)gw * 32 + lane] = o;
}

// ---------------- link scorer (h already relu'd) ----------------
__global__ void k_link(const int* __restrict__ eli, const float* __restrict__ Wp,
                       const float* __restrict__ bp, float* __restrict__ out) {
    __shared__ __align__(16) float swsum[CC];
    __shared__ float sb;
    int t = threadIdx.x;
    if (t < CC) swsum[t] = Wp[2 * t] + Wp[2 * t + 1];
    if (t == 0) sb = bp[0] + bp[1];
    __syncthreads();
    int gw = (blockIdx.x * blockDim.x + t) >> 5;
    int lane = t & 31;
    if (gw >= LL) return;
    int s = eli[gw], d = eli[LL + gw];
    const float4* hu = (const float4*)(g_h[1] + (size_t)s * CC);
    const float4* hi = (const float4*)(g_h[0] + (size_t)d * CC);
    float4 a = hu[lane], b = hi[lane];
    float4 w = ((const float4*)swsum)[lane];
    float acc = a.x * b.x * w.x + a.y * b.y * w.y + a.z * b.z * w.z + a.w * b.w * w.w;
    #pragma unroll
    for (int o = 16; o > 0; o >>= 1) acc += __shfl_down_sync(0xffffffffu, acc, o);
    if (lane == 0) out[gw] = acc + sb;
}

// ---------------- host launcher ----------------
extern "C" void kernel_launch(void* const* d_in, const int* in_sizes, int n_in,
                              void* d_out, int out_size) {
    (void)in_sizes; (void)n_in; (void)out_size;

    void *ph, *pds, *pdd;
    cudaGetSymbolAddress(&ph,  g_hist);
    cudaGetSymbolAddress(&pds, g_degs);
    cudaGetSymbolAddress(&pdd, g_degd);
    cudaMemsetAsync(ph,  0, sizeof(int) * 2 * NBIN, 0);
    cudaMemsetAsync(pds, 0, sizeof(int) * 2 * NN, 0);
    cudaMemsetAsync(pdd, 0, sizeof(int) * 2 * NN, 0);

    cudaFuncSetAttribute(k_gemm_tf32, cudaFuncAttributeMaxDynamicSharedMemorySize, 131072);

    const float* x0 = (const float*)d_in[0];
    const float* x1 = (const float*)d_in[1];
    const int*   e0 = (const int*)d_in[2];
    const int*   e1 = (const int*)d_in[3];

    RelParams r0 = { (const float*)d_in[6],  (const float*)d_in[7],
                     (const float*)d_in[8],  (const float*)d_in[9],
                     (const float*)d_in[10] };
    RelParams r1 = { (const float*)d_in[12], (const float*)d_in[13],
                     (const float*)d_in[14], (const float*)d_in[15],
                     (const float*)d_in[16] };

    dim3 gSD(10000 + (EE + 255) / 256, 2);
    k_scoredeg<<<gSD, 256>>>(x0, x1, (const float*)d_in[5], (const float*)d_in[11], e0, e1);

    k_select<<<2, 1024>>>(x0, x1);
    k_grumm<<<dim3(6, 2, 8), 256>>>(r0, r1);
    k_gate<<<dim3(CC, 2), CC>>>(r0, r1);

    k_scan1<<<dim3(SCAN_BLK, 2), 1024>>>();
    k_scan3<<<dim3(SCAN_BLK, 2), 1024>>>();
    dim3 gFill((EE + 255) / 256, 2);
    k_fill<<<gFill, 256>>>(e0, e1);

    k_gemm_tf32<<<dim3(GEMM_BLKS, 2), 256, 131072>>>(x0, x1);

    dim3 gAgg((NN * 32 + 255) / 256, 2);
    k_agg<<<gAgg, 256>>>();

    k_link<<<(LL * 32 + 255) / 256, 256>>>((const int*)d_in[4],
                                           (const float*)d_in[17],
                                           (const float*)d_in[18],
                                           (float*)d_out);
}